// round 5
// baseline (speedup 1.0000x reference)
#include <cuda_runtime.h>
#include <cuda_fp16.h>
#include <math.h>

// ---------------- problem constants ----------------
#define NMAX 50000
#define EMAX 1700000   // 1.6M edges + 50k self-loops

// ---------------- device scratch (no allocs allowed) ----------------
__device__ uint2    g_xw1h[NMAX * 32];   // 128 cols as half (4 halfs per lane-slot)
__device__ float    g_as1 [NMAX * 4];
__device__ float    g_ad1 [NMAX * 4];
__device__ float    g_h   [NMAX * 128];  // elu(normalized agg1 + b1), fp32
__device__ unsigned g_xw2h[NMAX * 32];   // 64 cols as half (2 per slot)
__device__ float    g_as2 [NMAX];
__device__ float    g_ad2 [NMAX];
__device__ float    g_out2[NMAX * 64];

// CSR by destination (built once per call, shared by both layers)
__device__ int g_cnt   [NMAX];
__device__ int g_rowst [NMAX + 1];
__device__ int g_cursor[NMAX];
__device__ int g_csrc  [EMAX];

__device__ __forceinline__ float lrelu(float z) { return z > 0.f ? z : 0.2f * z; }

// ---------------- CSR build ----------------
// counts start at 1: the self-loop for each node is folded in analytically
__global__ void k_init(const float* __restrict__ b2, float* __restrict__ dout, int n) {
    int i = blockIdx.x * blockDim.x + threadIdx.x;
    if (i < n)  g_cnt[i] = 1;
    if (i < 64) dout[i] = b2[i];
}

__global__ void k_hist(const int* __restrict__ ei, int E) {
    int t = blockIdx.x * blockDim.x + threadIdx.x;
    int nq = E >> 2;
    if (t < nq) {
        int4 d4 = ((const int4*)(ei + E))[t];
        atomicAdd(&g_cnt[d4.x], 1);
        atomicAdd(&g_cnt[d4.y], 1);
        atomicAdd(&g_cnt[d4.z], 1);
        atomicAdd(&g_cnt[d4.w], 1);
    } else if (t == nq) {
        for (int e = nq * 4; e < E; e++) atomicAdd(&g_cnt[ei[E + e]], 1);
    }
}

// single-block exclusive scan; also pre-places the self-loop entry per row
__global__ void k_scan(int n) {
    __shared__ int sm[1024];
    int t = threadIdx.x;
    int chunk = (n + 1023) / 1024;
    int beg = t * chunk, end = min(beg + chunk, n);
    int tot = 0;
    for (int i = beg; i < end; i++) tot += g_cnt[i];
    sm[t] = tot;
    __syncthreads();
    for (int off = 1; off < 1024; off <<= 1) {
        int v = (t >= off) ? sm[t - off] : 0;
        __syncthreads();
        sm[t] += v;
        __syncthreads();
    }
    int base = sm[t] - tot;
    for (int i = beg; i < end; i++) {
        g_rowst[i] = base;
        g_csrc[base] = i;          // self-loop goes first
        g_cursor[i] = base + 1;
        base += g_cnt[i];
    }
    if (t == 0) g_rowst[n] = sm[1023];
}

__global__ void k_scatter(const int* __restrict__ ei, int E) {
    int t = blockIdx.x * blockDim.x + threadIdx.x;
    int nq = E >> 2;
    if (t < nq) {
        int4 s4 = ((const int4*)ei)[t];
        int4 d4 = ((const int4*)(ei + E))[t];
        g_csrc[atomicAdd(&g_cursor[d4.x], 1)] = s4.x;
        g_csrc[atomicAdd(&g_cursor[d4.y], 1)] = s4.y;
        g_csrc[atomicAdd(&g_cursor[d4.z], 1)] = s4.z;
        g_csrc[atomicAdd(&g_cursor[d4.w], 1)] = s4.w;
    } else if (t == nq) {
        for (int e = nq * 4; e < E; e++)
            g_csrc[atomicAdd(&g_cursor[ei[E + e]], 1)] = ei[e];
    }
}

// ---------------- layer kernels ----------------
// xw1 = x @ W1 (fp16 out); a_src1/a_dst1 fp32. 4 nodes per warp.
__global__ void k_gemm1(const float* __restrict__ x, const float* __restrict__ W,
                        const float* __restrict__ asv, const float* __restrict__ adv, int n) {
    __shared__ float xs[32][128];
    int w = threadIdx.x >> 5, lane = threadIdx.x & 31;
    int node0 = blockIdx.x * 32 + w * 4;
    int c0 = lane * 4;
#pragma unroll
    for (int i = 0; i < 4; i++) {
        int nd = node0 + i;
        if (nd < n)
            ((float4*)xs[w * 4 + i])[lane] = *(const float4*)(x + (size_t)nd * 128 + c0);
    }
    __syncwarp();
    float4 acc0 = make_float4(0,0,0,0), acc1 = acc0, acc2 = acc0, acc3 = acc0;
    const float* wp = W + c0;
#pragma unroll 4
    for (int k = 0; k < 128; k++) {
        float4 wv = *(const float4*)(wp + k * 128);
        float x0 = xs[w*4+0][k], x1 = xs[w*4+1][k], x2 = xs[w*4+2][k], x3 = xs[w*4+3][k];
        acc0.x = fmaf(x0, wv.x, acc0.x); acc0.y = fmaf(x0, wv.y, acc0.y);
        acc0.z = fmaf(x0, wv.z, acc0.z); acc0.w = fmaf(x0, wv.w, acc0.w);
        acc1.x = fmaf(x1, wv.x, acc1.x); acc1.y = fmaf(x1, wv.y, acc1.y);
        acc1.z = fmaf(x1, wv.z, acc1.z); acc1.w = fmaf(x1, wv.w, acc1.w);
        acc2.x = fmaf(x2, wv.x, acc2.x); acc2.y = fmaf(x2, wv.y, acc2.y);
        acc2.z = fmaf(x2, wv.z, acc2.z); acc2.w = fmaf(x2, wv.w, acc2.w);
        acc3.x = fmaf(x3, wv.x, acc3.x); acc3.y = fmaf(x3, wv.y, acc3.y);
        acc3.z = fmaf(x3, wv.z, acc3.z); acc3.w = fmaf(x3, wv.w, acc3.w);
    }
    float4 av = *(const float4*)(asv + c0);
    float4 dv = *(const float4*)(adv + c0);
    float4 accs[4] = {acc0, acc1, acc2, acc3};
#pragma unroll
    for (int i = 0; i < 4; i++) {
        int nd = node0 + i;
        if (nd >= n) continue;
        float4 a = accs[i];
        __half2 p0 = __floats2half2_rn(a.x, a.y);
        __half2 p1 = __floats2half2_rn(a.z, a.w);
        uint2 packed;
        packed.x = *(unsigned*)&p0;
        packed.y = *(unsigned*)&p1;
        g_xw1h[nd * 32 + lane] = packed;
        float s = a.x * av.x + a.y * av.y + a.z * av.z + a.w * av.w;
        float d = a.x * dv.x + a.y * dv.y + a.z * dv.z + a.w * dv.w;
#pragma unroll
        for (int off = 4; off; off >>= 1) {
            s += __shfl_xor_sync(0xffffffffu, s, off);
            d += __shfl_xor_sync(0xffffffffu, d, off);
        }
        if ((lane & 7) == 0) {
            g_as1[nd * 4 + (lane >> 3)] = s;
            g_ad1[nd * 4 + (lane >> 3)] = d;
        }
    }
}

// gather agg layer1: warp per dst node; fp16 feature gather, fp32 math.
__global__ void k_agg1(const float* __restrict__ b1, int n) {
    int gt = blockIdx.x * blockDim.x + threadIdx.x;
    int nd = gt >> 5, lane = gt & 31;
    if (nd >= n) return;
    int h = lane >> 3, c0 = lane * 4;
    int beg = g_rowst[nd], end = g_rowst[nd + 1];
    float adh = g_ad1[nd * 4 + h];
    float4 acc = make_float4(0,0,0,0);
    float den = 0.f;
    int j = beg;
    for (; j + 3 < end; j += 4) {
        int s0 = g_csrc[j], s1 = g_csrc[j+1], s2 = g_csrc[j+2], s3 = g_csrc[j+3];
        float e0 = __expf(lrelu(g_as1[s0 * 4 + h] + adh));
        float e1 = __expf(lrelu(g_as1[s1 * 4 + h] + adh));
        float e2 = __expf(lrelu(g_as1[s2 * 4 + h] + adh));
        float e3 = __expf(lrelu(g_as1[s3 * 4 + h] + adh));
        uint2 r0 = g_xw1h[s0 * 32 + lane];
        uint2 r1 = g_xw1h[s1 * 32 + lane];
        uint2 r2 = g_xw1h[s2 * 32 + lane];
        uint2 r3 = g_xw1h[s3 * 32 + lane];
        float2 a0 = __half22float2(*(__half2*)&r0.x), b0 = __half22float2(*(__half2*)&r0.y);
        float2 a1 = __half22float2(*(__half2*)&r1.x), b1v = __half22float2(*(__half2*)&r1.y);
        float2 a2 = __half22float2(*(__half2*)&r2.x), b2v = __half22float2(*(__half2*)&r2.y);
        float2 a3 = __half22float2(*(__half2*)&r3.x), b3v = __half22float2(*(__half2*)&r3.y);
        acc.x = fmaf(e0, a0.x, acc.x); acc.y = fmaf(e0, a0.y, acc.y);
        acc.z = fmaf(e0, b0.x, acc.z); acc.w = fmaf(e0, b0.y, acc.w);
        acc.x = fmaf(e1, a1.x, acc.x); acc.y = fmaf(e1, a1.y, acc.y);
        acc.z = fmaf(e1, b1v.x, acc.z); acc.w = fmaf(e1, b1v.y, acc.w);
        acc.x = fmaf(e2, a2.x, acc.x); acc.y = fmaf(e2, a2.y, acc.y);
        acc.z = fmaf(e2, b2v.x, acc.z); acc.w = fmaf(e2, b2v.y, acc.w);
        acc.x = fmaf(e3, a3.x, acc.x); acc.y = fmaf(e3, a3.y, acc.y);
        acc.z = fmaf(e3, b3v.x, acc.z); acc.w = fmaf(e3, b3v.y, acc.w);
        den += (e0 + e1) + (e2 + e3);
    }
    for (; j < end; j++) {
        int s0 = g_csrc[j];
        float e0 = __expf(lrelu(g_as1[s0 * 4 + h] + adh));
        uint2 r0 = g_xw1h[s0 * 32 + lane];
        float2 a0 = __half22float2(*(__half2*)&r0.x), b0 = __half22float2(*(__half2*)&r0.y);
        acc.x = fmaf(e0, a0.x, acc.x); acc.y = fmaf(e0, a0.y, acc.y);
        acc.z = fmaf(e0, b0.x, acc.z); acc.w = fmaf(e0, b0.y, acc.w);
        den += e0;
    }
    float inv = 1.0f / (den + 1e-16f);
    float4 bv = *(const float4*)(b1 + c0);
    float4 hv;
    hv.x = acc.x * inv + bv.x; hv.x = hv.x > 0.f ? hv.x : expm1f(hv.x);
    hv.y = acc.y * inv + bv.y; hv.y = hv.y > 0.f ? hv.y : expm1f(hv.y);
    hv.z = acc.z * inv + bv.z; hv.z = hv.z > 0.f ? hv.z : expm1f(hv.z);
    hv.w = acc.w * inv + bv.w; hv.w = hv.w > 0.f ? hv.w : expm1f(hv.w);
    *(float4*)(g_h + (size_t)nd * 128 + c0) = hv;
}

// xw2 = h @ W2 (fp16 out); a_src2/a_dst2 fp32. 4 nodes per warp.
__global__ void k_gemm2(const float* __restrict__ W,
                        const float* __restrict__ asv, const float* __restrict__ adv, int n) {
    __shared__ float hs[32][128];
    int w = threadIdx.x >> 5, lane = threadIdx.x & 31;
    int node0 = blockIdx.x * 32 + w * 4;
    int c0 = lane * 4;
#pragma unroll
    for (int i = 0; i < 4; i++) {
        int nd = node0 + i;
        if (nd < n)
            ((float4*)hs[w * 4 + i])[lane] = *(const float4*)(g_h + (size_t)nd * 128 + c0);
    }
    __syncwarp();
    float2 acc0 = make_float2(0,0), acc1 = acc0, acc2 = acc0, acc3 = acc0;
    const float* wp = W + lane * 2;
#pragma unroll 4
    for (int k = 0; k < 128; k++) {
        float2 wv = *(const float2*)(wp + k * 64);
        float x0 = hs[w*4+0][k], x1 = hs[w*4+1][k], x2 = hs[w*4+2][k], x3 = hs[w*4+3][k];
        acc0.x = fmaf(x0, wv.x, acc0.x); acc0.y = fmaf(x0, wv.y, acc0.y);
        acc1.x = fmaf(x1, wv.x, acc1.x); acc1.y = fmaf(x1, wv.y, acc1.y);
        acc2.x = fmaf(x2, wv.x, acc2.x); acc2.y = fmaf(x2, wv.y, acc2.y);
        acc3.x = fmaf(x3, wv.x, acc3.x); acc3.y = fmaf(x3, wv.y, acc3.y);
    }
    float2 av = *(const float2*)(asv + lane * 2);
    float2 dv = *(const float2*)(adv + lane * 2);
    float2 accs[4] = {acc0, acc1, acc2, acc3};
#pragma unroll
    for (int i = 0; i < 4; i++) {
        int nd = node0 + i;
        if (nd >= n) continue;
        float2 a = accs[i];
        __half2 p = __floats2half2_rn(a.x, a.y);
        g_xw2h[nd * 32 + lane] = *(unsigned*)&p;
        float s = a.x * av.x + a.y * av.y;
        float d = a.x * dv.x + a.y * dv.y;
#pragma unroll
        for (int off = 16; off; off >>= 1) {
            s += __shfl_xor_sync(0xffffffffu, s, off);
            d += __shfl_xor_sync(0xffffffffu, d, off);
        }
        if (lane == 0) { g_as2[nd] = s; g_ad2[nd] = d; }
    }
}

// gather agg layer2: warp per dst node; fp16 gather; writes normalized out2.
__global__ void k_agg2(int n) {
    int gt = blockIdx.x * blockDim.x + threadIdx.x;
    int nd = gt >> 5, lane = gt & 31;
    if (nd >= n) return;
    int c0 = lane * 2;
    int beg = g_rowst[nd], end = g_rowst[nd + 1];
    float adh = g_ad2[nd];
    float2 acc = make_float2(0,0);
    float den = 0.f;
    int j = beg;
    for (; j + 3 < end; j += 4) {
        int s0 = g_csrc[j], s1 = g_csrc[j+1], s2 = g_csrc[j+2], s3 = g_csrc[j+3];
        float e0 = __expf(lrelu(g_as2[s0] + adh));
        float e1 = __expf(lrelu(g_as2[s1] + adh));
        float e2 = __expf(lrelu(g_as2[s2] + adh));
        float e3 = __expf(lrelu(g_as2[s3] + adh));
        unsigned r0 = g_xw2h[s0 * 32 + lane];
        unsigned r1 = g_xw2h[s1 * 32 + lane];
        unsigned r2 = g_xw2h[s2 * 32 + lane];
        unsigned r3 = g_xw2h[s3 * 32 + lane];
        float2 v0 = __half22float2(*(__half2*)&r0);
        float2 v1 = __half22float2(*(__half2*)&r1);
        float2 v2 = __half22float2(*(__half2*)&r2);
        float2 v3 = __half22float2(*(__half2*)&r3);
        acc.x = fmaf(e0, v0.x, acc.x); acc.y = fmaf(e0, v0.y, acc.y);
        acc.x = fmaf(e1, v1.x, acc.x); acc.y = fmaf(e1, v1.y, acc.y);
        acc.x = fmaf(e2, v2.x, acc.x); acc.y = fmaf(e2, v2.y, acc.y);
        acc.x = fmaf(e3, v3.x, acc.x); acc.y = fmaf(e3, v3.y, acc.y);
        den += (e0 + e1) + (e2 + e3);
    }
    for (; j < end; j++) {
        int s0 = g_csrc[j];
        float e0 = __expf(lrelu(g_as2[s0] + adh));
        unsigned r0 = g_xw2h[s0 * 32 + lane];
        float2 v0 = __half22float2(*(__half2*)&r0);
        acc.x = fmaf(e0, v0.x, acc.x); acc.y = fmaf(e0, v0.y, acc.y);
        den += e0;
    }
    float inv = 1.0f / (den + 1e-16f);
    *(float2*)(g_out2 + (size_t)nd * 64 + c0) = make_float2(acc.x * inv, acc.y * inv);
}

// final: dout[c] = b2[c] (seeded in init) + mean_n out2[n][c]
__global__ void k_final(float* __restrict__ dout, int n) {
    __shared__ float sm[256];
    int tid = threadIdx.x;
    float local = 0.f;
    float inv = 1.0f / (float)n;
    int total = n * 64;
    for (int i = blockIdx.x * 256 + tid; i < total; i += gridDim.x * 256)
        local += g_out2[i] * inv;
    sm[tid] = local;
    __syncthreads();
    if (tid < 64) {
        float s2 = sm[tid] + sm[tid + 64] + sm[tid + 128] + sm[tid + 192];
        atomicAdd(&dout[tid], s2);
    }
}

// ---------------- launch ----------------
extern "C" void kernel_launch(void* const* d_in, const int* in_sizes, int n_in,
                              void* d_out, int out_size) {
    const float* x   = (const float*)d_in[0];
    const int*   ei  = (const int*)d_in[1];
    const float* W1  = (const float*)d_in[2];
    const float* as1 = (const float*)d_in[3];
    const float* ad1 = (const float*)d_in[4];
    const float* b1  = (const float*)d_in[5];
    const float* W2  = (const float*)d_in[6];
    const float* as2 = (const float*)d_in[7];
    const float* ad2 = (const float*)d_in[8];
    const float* b2  = (const float*)d_in[9];
    float* out = (float*)d_out;

    int n = in_sizes[0] / 128;
    int E = in_sizes[1] / 2;
    int nq = (E >> 2) + 1;   // vector quads + tail thread

    k_init   <<<(n + 255) / 256, 256>>>(b2, out, n);
    k_hist   <<<(nq + 255) / 256, 256>>>(ei, E);
    k_scan   <<<1, 1024>>>(n);
    k_scatter<<<(nq + 255) / 256, 256>>>(ei, E);
    k_gemm1  <<<(n + 31) / 32, 256>>>(x, W1, as1, ad1, n);
    k_agg1   <<<(n + 7) / 8, 256>>>(b1, n);
    k_gemm2  <<<(n + 31) / 32, 256>>>(W2, as2, ad2, n);
    k_agg2   <<<(n + 7) / 8, 256>>>(n);
    k_final  <<<256, 256>>>(out, n);
}

// round 6
// speedup vs baseline: 1.0061x; 1.0061x over previous
#include <cuda_runtime.h>
#include <math.h>

// ---------------- problem constants ----------------
#define NMAX 50000
#define EMAX 1700000   // 1.6M edges + 50k self-loops

// ---------------- device scratch (no allocs allowed) ----------------
__device__ float g_xw1 [NMAX * 128];
__device__ float g_as1 [NMAX * 4];
__device__ float g_ad1 [NMAX * 4];
__device__ float g_h   [NMAX * 128];   // elu(normalized agg1 + b1)
__device__ float g_xw2 [NMAX * 64];
__device__ float g_as2 [NMAX];
__device__ float g_ad2 [NMAX];
__device__ float g_out2[NMAX * 64];

// CSR by destination (built once per call, shared by both layers)
__device__ int g_cnt   [NMAX];
__device__ int g_rowst [NMAX + 1];
__device__ int g_cursor[NMAX];
__device__ int g_csrc  [EMAX];

__device__ __forceinline__ float lrelu(float z) { return z > 0.f ? z : 0.2f * z; }

// ---------------- CSR build (round-4 proven versions) ----------------
__global__ void k_init(const float* __restrict__ b2, float* __restrict__ dout, int n) {
    int i = blockIdx.x * blockDim.x + threadIdx.x;
    if (i < n)  g_cnt[i] = 0;
    if (i < 64) dout[i] = b2[i];
}

__global__ void k_hist(const int* __restrict__ ei, int E, int Etot) {
    int e = blockIdx.x * blockDim.x + threadIdx.x;
    if (e >= Etot) return;
    int d = (e < E) ? ei[E + e] : (e - E);
    atomicAdd(&g_cnt[d], 1);
}

// single-block exclusive scan over n counts -> rowst[0..n], cursor = rowst
__global__ void k_scan(int n) {
    __shared__ int sm[1024];
    int t = threadIdx.x;
    int chunk = (n + 1023) / 1024;
    int beg = t * chunk, end = min(beg + chunk, n);
    int tot = 0;
    for (int i = beg; i < end; i++) tot += g_cnt[i];
    sm[t] = tot;
    __syncthreads();
    for (int off = 1; off < 1024; off <<= 1) {
        int v = (t >= off) ? sm[t - off] : 0;
        __syncthreads();
        sm[t] += v;
        __syncthreads();
    }
    int base = sm[t] - tot;
    for (int i = beg; i < end; i++) {
        g_rowst[i] = base;
        g_cursor[i] = base;
        base += g_cnt[i];
    }
    if (t == 0) g_rowst[n] = sm[1023];
}

__global__ void k_scatter(const int* __restrict__ ei, int E, int Etot) {
    int e = blockIdx.x * blockDim.x + threadIdx.x;
    if (e >= Etot) return;
    int s, d;
    if (e < E) { s = ei[e]; d = ei[E + e]; } else { s = d = e - E; }
    int pos = atomicAdd(&g_cursor[d], 1);
    g_csrc[pos] = s;
}

// ---------------- layer kernels ----------------
// xw1 = x @ W1 ; a_src1/a_dst1. 4 nodes per warp -> 4x W reuse per load.
__global__ void k_gemm1(const float* __restrict__ x, const float* __restrict__ W,
                        const float* __restrict__ asv, const float* __restrict__ adv, int n) {
    __shared__ float xs[32][128];
    int w = threadIdx.x >> 5, lane = threadIdx.x & 31;
    int node0 = blockIdx.x * 32 + w * 4;
    int c0 = lane * 4;
#pragma unroll
    for (int i = 0; i < 4; i++) {
        int nd = node0 + i;
        if (nd < n)
            ((float4*)xs[w * 4 + i])[lane] = *(const float4*)(x + (size_t)nd * 128 + c0);
    }
    __syncwarp();
    float4 acc0 = make_float4(0,0,0,0), acc1 = acc0, acc2 = acc0, acc3 = acc0;
    const float* wp = W + c0;
#pragma unroll 4
    for (int k = 0; k < 128; k++) {
        float4 wv = *(const float4*)(wp + k * 128);
        float x0 = xs[w*4+0][k], x1 = xs[w*4+1][k], x2 = xs[w*4+2][k], x3 = xs[w*4+3][k];
        acc0.x = fmaf(x0, wv.x, acc0.x); acc0.y = fmaf(x0, wv.y, acc0.y);
        acc0.z = fmaf(x0, wv.z, acc0.z); acc0.w = fmaf(x0, wv.w, acc0.w);
        acc1.x = fmaf(x1, wv.x, acc1.x); acc1.y = fmaf(x1, wv.y, acc1.y);
        acc1.z = fmaf(x1, wv.z, acc1.z); acc1.w = fmaf(x1, wv.w, acc1.w);
        acc2.x = fmaf(x2, wv.x, acc2.x); acc2.y = fmaf(x2, wv.y, acc2.y);
        acc2.z = fmaf(x2, wv.z, acc2.z); acc2.w = fmaf(x2, wv.w, acc2.w);
        acc3.x = fmaf(x3, wv.x, acc3.x); acc3.y = fmaf(x3, wv.y, acc3.y);
        acc3.z = fmaf(x3, wv.z, acc3.z); acc3.w = fmaf(x3, wv.w, acc3.w);
    }
    float4 av = *(const float4*)(asv + c0);
    float4 dv = *(const float4*)(adv + c0);
    float4 accs[4] = {acc0, acc1, acc2, acc3};
#pragma unroll
    for (int i = 0; i < 4; i++) {
        int nd = node0 + i;
        if (nd >= n) continue;
        float4 a = accs[i];
        *(float4*)(g_xw1 + (size_t)nd * 128 + c0) = a;
        float s = a.x * av.x + a.y * av.y + a.z * av.z + a.w * av.w;
        float d = a.x * dv.x + a.y * dv.y + a.z * dv.z + a.w * dv.w;
#pragma unroll
        for (int off = 4; off; off >>= 1) {
            s += __shfl_xor_sync(0xffffffffu, s, off);
            d += __shfl_xor_sync(0xffffffffu, d, off);
        }
        if ((lane & 7) == 0) {
            g_as1[nd * 4 + (lane >> 3)] = s;
            g_ad1[nd * 4 + (lane >> 3)] = d;
        }
    }
}

// gather agg layer1: 2 warps per dst node (edge range split), smem combine.
// epilogue writes h = elu(acc/den + b1).
__global__ void k_agg1(const float* __restrict__ b1, int n) {
    __shared__ float s_acc[4][128];
    __shared__ float s_den[4][4];
    int w = threadIdx.x >> 5, lane = threadIdx.x & 31;
    int slot = w >> 1, half = w & 1;
    int nd = blockIdx.x * 4 + slot;
    bool valid = nd < n;
    int h = lane >> 3, c0 = lane * 4;
    float4 acc = make_float4(0,0,0,0);
    float den = 0.f;
    if (valid) {
        int rbeg = g_rowst[nd], rend = g_rowst[nd + 1];
        int mid = (rbeg + rend + 1) >> 1;
        int beg = half ? mid : rbeg;
        int end = half ? rend : mid;
        float adh = g_ad1[nd * 4 + h];
        int j = beg;
        for (; j + 1 < end; j += 2) {
            int s0 = g_csrc[j], s1 = g_csrc[j + 1];
            float e0 = __expf(lrelu(g_as1[s0 * 4 + h] + adh));
            float e1 = __expf(lrelu(g_as1[s1 * 4 + h] + adh));
            float4 v0 = *(const float4*)(g_xw1 + (size_t)s0 * 128 + c0);
            float4 v1 = *(const float4*)(g_xw1 + (size_t)s1 * 128 + c0);
            acc.x = fmaf(e0, v0.x, acc.x); acc.y = fmaf(e0, v0.y, acc.y);
            acc.z = fmaf(e0, v0.z, acc.z); acc.w = fmaf(e0, v0.w, acc.w);
            acc.x = fmaf(e1, v1.x, acc.x); acc.y = fmaf(e1, v1.y, acc.y);
            acc.z = fmaf(e1, v1.z, acc.z); acc.w = fmaf(e1, v1.w, acc.w);
            den += e0 + e1;
        }
        if (j < end) {
            int s0 = g_csrc[j];
            float e0 = __expf(lrelu(g_as1[s0 * 4 + h] + adh));
            float4 v0 = *(const float4*)(g_xw1 + (size_t)s0 * 128 + c0);
            acc.x = fmaf(e0, v0.x, acc.x); acc.y = fmaf(e0, v0.y, acc.y);
            acc.z = fmaf(e0, v0.z, acc.z); acc.w = fmaf(e0, v0.w, acc.w);
            den += e0;
        }
    }
    if (half == 1 && valid) {
        *(float4*)&s_acc[slot][c0] = acc;
        if ((lane & 7) == 0) s_den[slot][h] = den;
    }
    __syncthreads();
    if (half == 0 && valid) {
        float4 o = *(const float4*)&s_acc[slot][c0];
        acc.x += o.x; acc.y += o.y; acc.z += o.z; acc.w += o.w;
        den += s_den[slot][h];
        float inv = 1.0f / (den + 1e-16f);
        float4 bv = *(const float4*)(b1 + c0);
        float4 hv;
        hv.x = acc.x * inv + bv.x; hv.x = hv.x > 0.f ? hv.x : expm1f(hv.x);
        hv.y = acc.y * inv + bv.y; hv.y = hv.y > 0.f ? hv.y : expm1f(hv.y);
        hv.z = acc.z * inv + bv.z; hv.z = hv.z > 0.f ? hv.z : expm1f(hv.z);
        hv.w = acc.w * inv + bv.w; hv.w = hv.w > 0.f ? hv.w : expm1f(hv.w);
        *(float4*)(g_h + (size_t)nd * 128 + c0) = hv;
    }
}

// xw2 = h @ W2; a_src2/a_dst2. 4 nodes per warp.
__global__ void k_gemm2(const float* __restrict__ W,
                        const float* __restrict__ asv, const float* __restrict__ adv, int n) {
    __shared__ float hs[32][128];
    int w = threadIdx.x >> 5, lane = threadIdx.x & 31;
    int node0 = blockIdx.x * 32 + w * 4;
    int c0 = lane * 4;
#pragma unroll
    for (int i = 0; i < 4; i++) {
        int nd = node0 + i;
        if (nd < n)
            ((float4*)hs[w * 4 + i])[lane] = *(const float4*)(g_h + (size_t)nd * 128 + c0);
    }
    __syncwarp();
    float2 acc0 = make_float2(0,0), acc1 = acc0, acc2 = acc0, acc3 = acc0;
    const float* wp = W + lane * 2;
#pragma unroll 4
    for (int k = 0; k < 128; k++) {
        float2 wv = *(const float2*)(wp + k * 64);
        float x0 = hs[w*4+0][k], x1 = hs[w*4+1][k], x2 = hs[w*4+2][k], x3 = hs[w*4+3][k];
        acc0.x = fmaf(x0, wv.x, acc0.x); acc0.y = fmaf(x0, wv.y, acc0.y);
        acc1.x = fmaf(x1, wv.x, acc1.x); acc1.y = fmaf(x1, wv.y, acc1.y);
        acc2.x = fmaf(x2, wv.x, acc2.x); acc2.y = fmaf(x2, wv.y, acc2.y);
        acc3.x = fmaf(x3, wv.x, acc3.x); acc3.y = fmaf(x3, wv.y, acc3.y);
    }
    float2 av = *(const float2*)(asv + lane * 2);
    float2 dv = *(const float2*)(adv + lane * 2);
    float2 accs[4] = {acc0, acc1, acc2, acc3};
#pragma unroll
    for (int i = 0; i < 4; i++) {
        int nd = node0 + i;
        if (nd >= n) continue;
        float2 a = accs[i];
        *(float2*)(g_xw2 + (size_t)nd * 64 + lane * 2) = a;
        float s = a.x * av.x + a.y * av.y;
        float d = a.x * dv.x + a.y * dv.y;
#pragma unroll
        for (int off = 16; off; off >>= 1) {
            s += __shfl_xor_sync(0xffffffffu, s, off);
            d += __shfl_xor_sync(0xffffffffu, d, off);
        }
        if (lane == 0) { g_as2[nd] = s; g_ad2[nd] = d; }
    }
}

// gather agg layer2: 2 warps per dst node, smem combine. writes normalized out2.
__global__ void k_agg2(int n) {
    __shared__ float s_acc[4][64];
    __shared__ float s_den[4];
    int w = threadIdx.x >> 5, lane = threadIdx.x & 31;
    int slot = w >> 1, half = w & 1;
    int nd = blockIdx.x * 4 + slot;
    bool valid = nd < n;
    int c0 = lane * 2;
    float2 acc = make_float2(0,0);
    float den = 0.f;
    if (valid) {
        int rbeg = g_rowst[nd], rend = g_rowst[nd + 1];
        int mid = (rbeg + rend + 1) >> 1;
        int beg = half ? mid : rbeg;
        int end = half ? rend : mid;
        float adh = g_ad2[nd];
        int j = beg;
        for (; j + 1 < end; j += 2) {
            int s0 = g_csrc[j], s1 = g_csrc[j + 1];
            float e0 = __expf(lrelu(g_as2[s0] + adh));
            float e1 = __expf(lrelu(g_as2[s1] + adh));
            float2 v0 = *(const float2*)(g_xw2 + (size_t)s0 * 64 + c0);
            float2 v1 = *(const float2*)(g_xw2 + (size_t)s1 * 64 + c0);
            acc.x = fmaf(e0, v0.x, acc.x); acc.y = fmaf(e0, v0.y, acc.y);
            acc.x = fmaf(e1, v1.x, acc.x); acc.y = fmaf(e1, v1.y, acc.y);
            den += e0 + e1;
        }
        if (j < end) {
            int s0 = g_csrc[j];
            float e0 = __expf(lrelu(g_as2[s0] + adh));
            float2 v0 = *(const float2*)(g_xw2 + (size_t)s0 * 64 + c0);
            acc.x = fmaf(e0, v0.x, acc.x); acc.y = fmaf(e0, v0.y, acc.y);
            den += e0;
        }
    }
    if (half == 1 && valid) {
        *(float2*)&s_acc[slot][c0] = acc;
        if (lane == 0) s_den[slot] = den;
    }
    __syncthreads();
    if (half == 0 && valid) {
        float2 o = *(const float2*)&s_acc[slot][c0];
        acc.x += o.x; acc.y += o.y;
        den += s_den[slot];
        float inv = 1.0f / (den + 1e-16f);
        *(float2*)(g_out2 + (size_t)nd * 64 + c0) = make_float2(acc.x * inv, acc.y * inv);
    }
}

// final: dout[c] = b2[c] (seeded in init) + mean_n out2[n][c]
__global__ void k_final(float* __restrict__ dout, int n) {
    __shared__ float sm[256];
    int tid = threadIdx.x;
    float local = 0.f;
    float inv = 1.0f / (float)n;
    int total = n * 64;
    for (int i = blockIdx.x * 256 + tid; i < total; i += gridDim.x * 256)
        local += g_out2[i] * inv;
    sm[tid] = local;
    __syncthreads();
    if (tid < 64) {
        float s2 = sm[tid] + sm[tid + 64] + sm[tid + 128] + sm[tid + 192];
        atomicAdd(&dout[tid], s2);
    }
}

// ---------------- launch ----------------
extern "C" void kernel_launch(void* const* d_in, const int* in_sizes, int n_in,
                              void* d_out, int out_size) {
    const float* x   = (const float*)d_in[0];
    const int*   ei  = (const int*)d_in[1];
    const float* W1  = (const float*)d_in[2];
    const float* as1 = (const float*)d_in[3];
    const float* ad1 = (const float*)d_in[4];
    const float* b1  = (const float*)d_in[5];
    const float* W2  = (const float*)d_in[6];
    const float* as2 = (const float*)d_in[7];
    const float* ad2 = (const float*)d_in[8];
    const float* b2  = (const float*)d_in[9];
    float* out = (float*)d_out;

    int n = in_sizes[0] / 128;
    int E = in_sizes[1] / 2;
    int Etot = E + n;

    k_init   <<<(n + 255) / 256, 256>>>(b2, out, n);
    k_hist   <<<(Etot + 255) / 256, 256>>>(ei, E, Etot);
    k_scan   <<<1, 1024>>>(n);
    k_scatter<<<(Etot + 255) / 256, 256>>>(ei, E, Etot);
    k_gemm1  <<<(n + 31) / 32, 256>>>(x, W1, as1, ad1, n);
    k_agg1   <<<(n + 3) / 4, 256>>>(b1, n);
    k_gemm2  <<<(n + 31) / 32, 256>>>(W2, as2, ad2, n);
    k_agg2   <<<(n + 3) / 4, 256>>>(n);
    k_final  <<<256, 256>>>(out, n);
}

// round 7
// speedup vs baseline: 1.1485x; 1.1416x over previous
#include <cuda_runtime.h>
#include <math.h>

// ---------------- problem constants ----------------
#define NMAX 50000
#define EMAX 1700000   // 1.6M edges + 50k self-loops

// ---------------- device scratch (no allocs allowed) ----------------
__device__ float g_xw1 [NMAX * 128];
__device__ float g_as1 [NMAX * 4];
__device__ float g_ad1 [NMAX * 4];
__device__ float g_h   [NMAX * 128];   // elu(normalized agg1 + b1)
__device__ float g_xw2 [NMAX * 64];
__device__ float g_as2 [NMAX];
__device__ float g_ad2 [NMAX];
__device__ float g_out2[NMAX * 64];

// CSR by destination (built once per call, shared by both layers)
__device__ int g_cnt   [NMAX];
__device__ int g_rowst [NMAX + 1];
__device__ int g_cursor[NMAX];
__device__ int g_csrc  [EMAX];

__device__ __forceinline__ float lrelu(float z) { return z > 0.f ? z : 0.2f * z; }

// ---------------- CSR build (round-4 proven versions) ----------------
__global__ void k_init(const float* __restrict__ b2, float* __restrict__ dout, int n) {
    int i = blockIdx.x * blockDim.x + threadIdx.x;
    if (i < n)  g_cnt[i] = 0;
    if (i < 64) dout[i] = b2[i];
}

__global__ void k_hist(const int* __restrict__ ei, int E, int Etot) {
    int e = blockIdx.x * blockDim.x + threadIdx.x;
    if (e >= Etot) return;
    int d = (e < E) ? ei[E + e] : (e - E);
    atomicAdd(&g_cnt[d], 1);
}

// single-block exclusive scan over n counts -> rowst[0..n], cursor = rowst
__global__ void k_scan(int n) {
    __shared__ int sm[1024];
    int t = threadIdx.x;
    int chunk = (n + 1023) / 1024;
    int beg = t * chunk, end = min(beg + chunk, n);
    int tot = 0;
    for (int i = beg; i < end; i++) tot += g_cnt[i];
    sm[t] = tot;
    __syncthreads();
    for (int off = 1; off < 1024; off <<= 1) {
        int v = (t >= off) ? sm[t - off] : 0;
        __syncthreads();
        sm[t] += v;
        __syncthreads();
    }
    int base = sm[t] - tot;
    for (int i = beg; i < end; i++) {
        g_rowst[i] = base;
        g_cursor[i] = base;
        base += g_cnt[i];
    }
    if (t == 0) g_rowst[n] = sm[1023];
}

__global__ void k_scatter(const int* __restrict__ ei, int E, int Etot) {
    int e = blockIdx.x * blockDim.x + threadIdx.x;
    if (e >= Etot) return;
    int s, d;
    if (e < E) { s = ei[e]; d = ei[E + e]; } else { s = d = e - E; }
    int pos = atomicAdd(&g_cursor[d], 1);
    g_csrc[pos] = s;
}

// ---------------- layer kernels ----------------
// xw1 = x @ W1 ; a_src1/a_dst1. 4 nodes per warp -> 4x W reuse per load.
__global__ void k_gemm1(const float* __restrict__ x, const float* __restrict__ W,
                        const float* __restrict__ asv, const float* __restrict__ adv, int n) {
    __shared__ float xs[32][128];
    int w = threadIdx.x >> 5, lane = threadIdx.x & 31;
    int node0 = blockIdx.x * 32 + w * 4;
    int c0 = lane * 4;
#pragma unroll
    for (int i = 0; i < 4; i++) {
        int nd = node0 + i;
        if (nd < n)
            ((float4*)xs[w * 4 + i])[lane] = *(const float4*)(x + (size_t)nd * 128 + c0);
    }
    __syncwarp();
    float4 acc0 = make_float4(0,0,0,0), acc1 = acc0, acc2 = acc0, acc3 = acc0;
    const float* wp = W + c0;
#pragma unroll 4
    for (int k = 0; k < 128; k++) {
        float4 wv = *(const float4*)(wp + k * 128);
        float x0 = xs[w*4+0][k], x1 = xs[w*4+1][k], x2 = xs[w*4+2][k], x3 = xs[w*4+3][k];
        acc0.x = fmaf(x0, wv.x, acc0.x); acc0.y = fmaf(x0, wv.y, acc0.y);
        acc0.z = fmaf(x0, wv.z, acc0.z); acc0.w = fmaf(x0, wv.w, acc0.w);
        acc1.x = fmaf(x1, wv.x, acc1.x); acc1.y = fmaf(x1, wv.y, acc1.y);
        acc1.z = fmaf(x1, wv.z, acc1.z); acc1.w = fmaf(x1, wv.w, acc1.w);
        acc2.x = fmaf(x2, wv.x, acc2.x); acc2.y = fmaf(x2, wv.y, acc2.y);
        acc2.z = fmaf(x2, wv.z, acc2.z); acc2.w = fmaf(x2, wv.w, acc2.w);
        acc3.x = fmaf(x3, wv.x, acc3.x); acc3.y = fmaf(x3, wv.y, acc3.y);
        acc3.z = fmaf(x3, wv.z, acc3.z); acc3.w = fmaf(x3, wv.w, acc3.w);
    }
    float4 av = *(const float4*)(asv + c0);
    float4 dv = *(const float4*)(adv + c0);
    float4 accs[4] = {acc0, acc1, acc2, acc3};
#pragma unroll
    for (int i = 0; i < 4; i++) {
        int nd = node0 + i;
        if (nd >= n) continue;
        float4 a = accs[i];
        *(float4*)(g_xw1 + (size_t)nd * 128 + c0) = a;
        float s = a.x * av.x + a.y * av.y + a.z * av.z + a.w * av.w;
        float d = a.x * dv.x + a.y * dv.y + a.z * dv.z + a.w * dv.w;
#pragma unroll
        for (int off = 4; off; off >>= 1) {
            s += __shfl_xor_sync(0xffffffffu, s, off);
            d += __shfl_xor_sync(0xffffffffu, d, off);
        }
        if ((lane & 7) == 0) {
            g_as1[nd * 4 + (lane >> 3)] = s;
            g_ad1[nd * 4 + (lane >> 3)] = d;
        }
    }
}

// gather agg layer1: warp per dst node (R4 structure), 4-deep unroll for MLP.
// epilogue writes h = elu(acc/den + b1).
__global__ void k_agg1(const float* __restrict__ b1, int n) {
    int gt = blockIdx.x * blockDim.x + threadIdx.x;
    int nd = gt >> 5, lane = gt & 31;
    if (nd >= n) return;
    int h = lane >> 3, c0 = lane * 4;
    int beg = g_rowst[nd], end = g_rowst[nd + 1];
    float adh = g_ad1[nd * 4 + h];
    float4 acc = make_float4(0,0,0,0);
    float den = 0.f;
    int j = beg;
    for (; j + 3 < end; j += 4) {
        int s0 = g_csrc[j], s1 = g_csrc[j+1], s2 = g_csrc[j+2], s3 = g_csrc[j+3];
        float e0 = __expf(lrelu(g_as1[s0 * 4 + h] + adh));
        float e1 = __expf(lrelu(g_as1[s1 * 4 + h] + adh));
        float e2 = __expf(lrelu(g_as1[s2 * 4 + h] + adh));
        float e3 = __expf(lrelu(g_as1[s3 * 4 + h] + adh));
        float4 v0 = *(const float4*)(g_xw1 + (size_t)s0 * 128 + c0);
        float4 v1 = *(const float4*)(g_xw1 + (size_t)s1 * 128 + c0);
        float4 v2 = *(const float4*)(g_xw1 + (size_t)s2 * 128 + c0);
        float4 v3 = *(const float4*)(g_xw1 + (size_t)s3 * 128 + c0);
        acc.x = fmaf(e0, v0.x, acc.x); acc.y = fmaf(e0, v0.y, acc.y);
        acc.z = fmaf(e0, v0.z, acc.z); acc.w = fmaf(e0, v0.w, acc.w);
        acc.x = fmaf(e1, v1.x, acc.x); acc.y = fmaf(e1, v1.y, acc.y);
        acc.z = fmaf(e1, v1.z, acc.z); acc.w = fmaf(e1, v1.w, acc.w);
        acc.x = fmaf(e2, v2.x, acc.x); acc.y = fmaf(e2, v2.y, acc.y);
        acc.z = fmaf(e2, v2.z, acc.z); acc.w = fmaf(e2, v2.w, acc.w);
        acc.x = fmaf(e3, v3.x, acc.x); acc.y = fmaf(e3, v3.y, acc.y);
        acc.z = fmaf(e3, v3.z, acc.z); acc.w = fmaf(e3, v3.w, acc.w);
        den += (e0 + e1) + (e2 + e3);
    }
    for (; j < end; j++) {
        int s0 = g_csrc[j];
        float e0 = __expf(lrelu(g_as1[s0 * 4 + h] + adh));
        float4 v0 = *(const float4*)(g_xw1 + (size_t)s0 * 128 + c0);
        acc.x = fmaf(e0, v0.x, acc.x); acc.y = fmaf(e0, v0.y, acc.y);
        acc.z = fmaf(e0, v0.z, acc.z); acc.w = fmaf(e0, v0.w, acc.w);
        den += e0;
    }
    float inv = 1.0f / (den + 1e-16f);
    float4 bv = *(const float4*)(b1 + c0);
    float4 hv;
    hv.x = acc.x * inv + bv.x; hv.x = hv.x > 0.f ? hv.x : expm1f(hv.x);
    hv.y = acc.y * inv + bv.y; hv.y = hv.y > 0.f ? hv.y : expm1f(hv.y);
    hv.z = acc.z * inv + bv.z; hv.z = hv.z > 0.f ? hv.z : expm1f(hv.z);
    hv.w = acc.w * inv + bv.w; hv.w = hv.w > 0.f ? hv.w : expm1f(hv.w);
    *(float4*)(g_h + (size_t)nd * 128 + c0) = hv;
}

// xw2 = h @ W2; a_src2/a_dst2. 4 nodes per warp.
__global__ void k_gemm2(const float* __restrict__ W,
                        const float* __restrict__ asv, const float* __restrict__ adv, int n) {
    __shared__ float hs[32][128];
    int w = threadIdx.x >> 5, lane = threadIdx.x & 31;
    int node0 = blockIdx.x * 32 + w * 4;
    int c0 = lane * 4;
#pragma unroll
    for (int i = 0; i < 4; i++) {
        int nd = node0 + i;
        if (nd < n)
            ((float4*)hs[w * 4 + i])[lane] = *(const float4*)(g_h + (size_t)nd * 128 + c0);
    }
    __syncwarp();
    float2 acc0 = make_float2(0,0), acc1 = acc0, acc2 = acc0, acc3 = acc0;
    const float* wp = W + lane * 2;
#pragma unroll 4
    for (int k = 0; k < 128; k++) {
        float2 wv = *(const float2*)(wp + k * 64);
        float x0 = hs[w*4+0][k], x1 = hs[w*4+1][k], x2 = hs[w*4+2][k], x3 = hs[w*4+3][k];
        acc0.x = fmaf(x0, wv.x, acc0.x); acc0.y = fmaf(x0, wv.y, acc0.y);
        acc1.x = fmaf(x1, wv.x, acc1.x); acc1.y = fmaf(x1, wv.y, acc1.y);
        acc2.x = fmaf(x2, wv.x, acc2.x); acc2.y = fmaf(x2, wv.y, acc2.y);
        acc3.x = fmaf(x3, wv.x, acc3.x); acc3.y = fmaf(x3, wv.y, acc3.y);
    }
    float2 av = *(const float2*)(asv + lane * 2);
    float2 dv = *(const float2*)(adv + lane * 2);
    float2 accs[4] = {acc0, acc1, acc2, acc3};
#pragma unroll
    for (int i = 0; i < 4; i++) {
        int nd = node0 + i;
        if (nd >= n) continue;
        float2 a = accs[i];
        *(float2*)(g_xw2 + (size_t)nd * 64 + lane * 2) = a;
        float s = a.x * av.x + a.y * av.y;
        float d = a.x * dv.x + a.y * dv.y;
#pragma unroll
        for (int off = 16; off; off >>= 1) {
            s += __shfl_xor_sync(0xffffffffu, s, off);
            d += __shfl_xor_sync(0xffffffffu, d, off);
        }
        if (lane == 0) { g_as2[nd] = s; g_ad2[nd] = d; }
    }
}

// gather agg layer2: warp per dst node (R4 structure, 2-unroll control).
__global__ void k_agg2(int n) {
    int gt = blockIdx.x * blockDim.x + threadIdx.x;
    int nd = gt >> 5, lane = gt & 31;
    if (nd >= n) return;
    int c0 = lane * 2;
    int beg = g_rowst[nd], end = g_rowst[nd + 1];
    float adh = g_ad2[nd];
    float2 acc = make_float2(0,0);
    float den = 0.f;
    int j = beg;
    for (; j + 1 < end; j += 2) {
        int s0 = g_csrc[j], s1 = g_csrc[j + 1];
        float e0 = __expf(lrelu(g_as2[s0] + adh));
        float e1 = __expf(lrelu(g_as2[s1] + adh));
        float2 v0 = *(const float2*)(g_xw2 + (size_t)s0 * 64 + c0);
        float2 v1 = *(const float2*)(g_xw2 + (size_t)s1 * 64 + c0);
        acc.x = fmaf(e0, v0.x, acc.x); acc.y = fmaf(e0, v0.y, acc.y);
        acc.x = fmaf(e1, v1.x, acc.x); acc.y = fmaf(e1, v1.y, acc.y);
        den += e0 + e1;
    }
    if (j < end) {
        int s0 = g_csrc[j];
        float e0 = __expf(lrelu(g_as2[s0] + adh));
        float2 v0 = *(const float2*)(g_xw2 + (size_t)s0 * 64 + c0);
        acc.x = fmaf(e0, v0.x, acc.x); acc.y = fmaf(e0, v0.y, acc.y);
        den += e0;
    }
    float inv = 1.0f / (den + 1e-16f);
    *(float2*)(g_out2 + (size_t)nd * 64 + c0) = make_float2(acc.x * inv, acc.y * inv);
}

// final: dout[c] = b2[c] (seeded in init) + mean_n out2[n][c]
__global__ void k_final(float* __restrict__ dout, int n) {
    __shared__ float sm[256];
    int tid = threadIdx.x;
    float local = 0.f;
    float inv = 1.0f / (float)n;
    int total = n * 64;
    for (int i = blockIdx.x * 256 + tid; i < total; i += gridDim.x * 256)
        local += g_out2[i] * inv;
    sm[tid] = local;
    __syncthreads();
    if (tid < 64) {
        float s2 = sm[tid] + sm[tid + 64] + sm[tid + 128] + sm[tid + 192];
        atomicAdd(&dout[tid], s2);
    }
}

// ---------------- launch ----------------
extern "C" void kernel_launch(void* const* d_in, const int* in_sizes, int n_in,
                              void* d_out, int out_size) {
    const float* x   = (const float*)d_in[0];
    const int*   ei  = (const int*)d_in[1];
    const float* W1  = (const float*)d_in[2];
    const float* as1 = (const float*)d_in[3];
    const float* ad1 = (const float*)d_in[4];
    const float* b1  = (const float*)d_in[5];
    const float* W2  = (const float*)d_in[6];
    const float* as2 = (const float*)d_in[7];
    const float* ad2 = (const float*)d_in[8];
    const float* b2  = (const float*)d_in[9];
    float* out = (float*)d_out;

    int n = in_sizes[0] / 128;
    int E = in_sizes[1] / 2;
    int Etot = E + n;

    // one-time stream/event resources (no device-memory allocation; the
    // launched work is identical on every call)
    static cudaStream_t s2 = nullptr;
    static cudaEvent_t evFork = nullptr, evJoin = nullptr;
    if (s2 == nullptr) {
        cudaStreamCreateWithFlags(&s2, cudaStreamNonBlocking);
        cudaEventCreateWithFlags(&evFork, cudaEventDisableTiming);
        cudaEventCreateWithFlags(&evJoin, cudaEventDisableTiming);
    }

    // fork: gemm1 runs on s2 concurrently with the CSR build on the main stream
    cudaEventRecord(evFork, 0);
    cudaStreamWaitEvent(s2, evFork, 0);
    k_gemm1<<<(n + 31) / 32, 256, 0, s2>>>(x, W1, as1, ad1, n);
    cudaEventRecord(evJoin, s2);

    // CSR build chain on the main stream
    k_init   <<<(n + 255) / 256, 256>>>(b2, out, n);
    k_hist   <<<(Etot + 255) / 256, 256>>>(ei, E, Etot);
    k_scan   <<<1, 1024>>>(n);
    k_scatter<<<(Etot + 255) / 256, 256>>>(ei, E, Etot);

    // join: agg1 needs both CSR and gemm1 outputs
    cudaStreamWaitEvent(0, evJoin, 0);
    k_agg1 <<<(n + 7) / 8, 256>>>(b1, n);
    k_gemm2<<<(n + 31) / 32, 256>>>(W2, as2, ad2, n);
    k_agg2 <<<(n + 7) / 8, 256>>>(n);
    k_final<<<256, 256>>>(out, n);
}

// round 8
// speedup vs baseline: 1.4750x; 1.2844x over previous
#include <cuda_runtime.h>
#include <math.h>

// ---------------- problem constants ----------------
#define NMAX 50000
#define EMAX 1700000   // 1.6M edges + 50k self-loops
#define SCAN_BLK 512
#define MAX_SCAN_BLOCKS 128   // ceil(NMAX/SCAN_BLK) = 98

// ---------------- device scratch (no allocs allowed) ----------------
__device__ float g_xw1 [NMAX * 128];
__device__ float g_as1 [NMAX * 4];
__device__ float g_ad1 [NMAX * 4];
__device__ float g_h   [NMAX * 128];   // elu(normalized agg1 + b1)
__device__ float g_xw2 [NMAX * 64];
__device__ float g_as2 [NMAX];
__device__ float g_ad2 [NMAX];
__device__ float g_out2[NMAX * 64];

// CSR by destination (built once per call, shared by both layers)
__device__ int g_cnt   [NMAX];
__device__ int g_excl  [NMAX];
__device__ int g_blksum[MAX_SCAN_BLOCKS];
__device__ int g_blkoff[MAX_SCAN_BLOCKS];
__device__ int g_rowst [NMAX + 1];
__device__ int g_cursor[NMAX];
__device__ int g_csrc  [EMAX];

__device__ __forceinline__ float lrelu(float z) { return z > 0.f ? z : 0.2f * z; }

// ---------------- CSR build ----------------
__global__ void k_init(const float* __restrict__ b2, float* __restrict__ dout, int n) {
    int i = blockIdx.x * blockDim.x + threadIdx.x;
    if (i < n)  g_cnt[i] = 0;
    if (i < 64) dout[i] = b2[i];
}

__global__ void k_hist(const int* __restrict__ ei, int E, int Etot) {
    int e = blockIdx.x * blockDim.x + threadIdx.x;
    if (e >= Etot) return;
    int d = (e < E) ? ei[E + e] : (e - E);
    atomicAdd(&g_cnt[d], 1);
}

// two-level scan, stage 1: per-block exclusive prefix + block totals
__global__ void k_scan_local(int n) {
    __shared__ int sm[SCAN_BLK];
    int t = threadIdx.x;
    int i = blockIdx.x * SCAN_BLK + t;
    int v = (i < n) ? g_cnt[i] : 0;
    sm[t] = v;
    __syncthreads();
    for (int off = 1; off < SCAN_BLK; off <<= 1) {
        int u = (t >= off) ? sm[t - off] : 0;
        __syncthreads();
        sm[t] += u;
        __syncthreads();
    }
    if (i < n) g_excl[i] = sm[t] - v;
    if (t == SCAN_BLK - 1) g_blksum[blockIdx.x] = sm[SCAN_BLK - 1];
}

// stage 2: scan block totals (nb <= 128), write grand total to rowst[n]
__global__ void k_scan_spine(int nb, int n) {
    __shared__ int sm[MAX_SCAN_BLOCKS];
    int t = threadIdx.x;
    int v = (t < nb) ? g_blksum[t] : 0;
    sm[t] = v;
    __syncthreads();
    for (int off = 1; off < MAX_SCAN_BLOCKS; off <<= 1) {
        int u = (t >= off) ? sm[t - off] : 0;
        __syncthreads();
        sm[t] += u;
        __syncthreads();
    }
    if (t < nb) g_blkoff[t] = sm[t] - v;
    if (t == MAX_SCAN_BLOCKS - 1) g_rowst[n] = sm[MAX_SCAN_BLOCKS - 1];
}

// stage 3: combine, write rowst + cursor
__global__ void k_scan_add(int n) {
    int i = blockIdx.x * blockDim.x + threadIdx.x;
    if (i >= n) return;
    int base = g_excl[i] + g_blkoff[i / SCAN_BLK];
    g_rowst[i] = base;
    g_cursor[i] = base;
}

__global__ void k_scatter(const int* __restrict__ ei, int E, int Etot) {
    int e = blockIdx.x * blockDim.x + threadIdx.x;
    if (e >= Etot) return;
    int s, d;
    if (e < E) { s = ei[e]; d = ei[E + e]; } else { s = d = e - E; }
    int pos = atomicAdd(&g_cursor[d], 1);
    g_csrc[pos] = s;
}

// ---------------- layer kernels ----------------
// xw1 = x @ W1 ; a_src1/a_dst1. 4 nodes per warp -> 4x W reuse per load.
__global__ void k_gemm1(const float* __restrict__ x, const float* __restrict__ W,
                        const float* __restrict__ asv, const float* __restrict__ adv, int n) {
    __shared__ float xs[32][128];
    int w = threadIdx.x >> 5, lane = threadIdx.x & 31;
    int node0 = blockIdx.x * 32 + w * 4;
    int c0 = lane * 4;
#pragma unroll
    for (int i = 0; i < 4; i++) {
        int nd = node0 + i;
        if (nd < n)
            ((float4*)xs[w * 4 + i])[lane] = *(const float4*)(x + (size_t)nd * 128 + c0);
    }
    __syncwarp();
    float4 acc0 = make_float4(0,0,0,0), acc1 = acc0, acc2 = acc0, acc3 = acc0;
    const float* wp = W + c0;
#pragma unroll 4
    for (int k = 0; k < 128; k++) {
        float4 wv = *(const float4*)(wp + k * 128);
        float x0 = xs[w*4+0][k], x1 = xs[w*4+1][k], x2 = xs[w*4+2][k], x3 = xs[w*4+3][k];
        acc0.x = fmaf(x0, wv.x, acc0.x); acc0.y = fmaf(x0, wv.y, acc0.y);
        acc0.z = fmaf(x0, wv.z, acc0.z); acc0.w = fmaf(x0, wv.w, acc0.w);
        acc1.x = fmaf(x1, wv.x, acc1.x); acc1.y = fmaf(x1, wv.y, acc1.y);
        acc1.z = fmaf(x1, wv.z, acc1.z); acc1.w = fmaf(x1, wv.w, acc1.w);
        acc2.x = fmaf(x2, wv.x, acc2.x); acc2.y = fmaf(x2, wv.y, acc2.y);
        acc2.z = fmaf(x2, wv.z, acc2.z); acc2.w = fmaf(x2, wv.w, acc2.w);
        acc3.x = fmaf(x3, wv.x, acc3.x); acc3.y = fmaf(x3, wv.y, acc3.y);
        acc3.z = fmaf(x3, wv.z, acc3.z); acc3.w = fmaf(x3, wv.w, acc3.w);
    }
    float4 av = *(const float4*)(asv + c0);
    float4 dv = *(const float4*)(adv + c0);
    float4 accs[4] = {acc0, acc1, acc2, acc3};
#pragma unroll
    for (int i = 0; i < 4; i++) {
        int nd = node0 + i;
        if (nd >= n) continue;
        float4 a = accs[i];
        *(float4*)(g_xw1 + (size_t)nd * 128 + c0) = a;
        float s = a.x * av.x + a.y * av.y + a.z * av.z + a.w * av.w;
        float d = a.x * dv.x + a.y * dv.y + a.z * dv.z + a.w * dv.w;
#pragma unroll
        for (int off = 4; off; off >>= 1) {
            s += __shfl_xor_sync(0xffffffffu, s, off);
            d += __shfl_xor_sync(0xffffffffu, d, off);
        }
        if ((lane & 7) == 0) {
            g_as1[nd * 4 + (lane >> 3)] = s;
            g_ad1[nd * 4 + (lane >> 3)] = d;
        }
    }
}

// gather agg layer1: warp per dst node, 4-deep unroll for MLP.
// epilogue writes h = elu(acc/den + b1).
__global__ void k_agg1(const float* __restrict__ b1, int n) {
    int gt = blockIdx.x * blockDim.x + threadIdx.x;
    int nd = gt >> 5, lane = gt & 31;
    if (nd >= n) return;
    int h = lane >> 3, c0 = lane * 4;
    int beg = g_rowst[nd], end = g_rowst[nd + 1];
    float adh = g_ad1[nd * 4 + h];
    float4 acc = make_float4(0,0,0,0);
    float den = 0.f;
    int j = beg;
    for (; j + 3 < end; j += 4) {
        int s0 = g_csrc[j], s1 = g_csrc[j+1], s2 = g_csrc[j+2], s3 = g_csrc[j+3];
        float e0 = __expf(lrelu(g_as1[s0 * 4 + h] + adh));
        float e1 = __expf(lrelu(g_as1[s1 * 4 + h] + adh));
        float e2 = __expf(lrelu(g_as1[s2 * 4 + h] + adh));
        float e3 = __expf(lrelu(g_as1[s3 * 4 + h] + adh));
        float4 v0 = *(const float4*)(g_xw1 + (size_t)s0 * 128 + c0);
        float4 v1 = *(const float4*)(g_xw1 + (size_t)s1 * 128 + c0);
        float4 v2 = *(const float4*)(g_xw1 + (size_t)s2 * 128 + c0);
        float4 v3 = *(const float4*)(g_xw1 + (size_t)s3 * 128 + c0);
        acc.x = fmaf(e0, v0.x, acc.x); acc.y = fmaf(e0, v0.y, acc.y);
        acc.z = fmaf(e0, v0.z, acc.z); acc.w = fmaf(e0, v0.w, acc.w);
        acc.x = fmaf(e1, v1.x, acc.x); acc.y = fmaf(e1, v1.y, acc.y);
        acc.z = fmaf(e1, v1.z, acc.z); acc.w = fmaf(e1, v1.w, acc.w);
        acc.x = fmaf(e2, v2.x, acc.x); acc.y = fmaf(e2, v2.y, acc.y);
        acc.z = fmaf(e2, v2.z, acc.z); acc.w = fmaf(e2, v2.w, acc.w);
        acc.x = fmaf(e3, v3.x, acc.x); acc.y = fmaf(e3, v3.y, acc.y);
        acc.z = fmaf(e3, v3.z, acc.z); acc.w = fmaf(e3, v3.w, acc.w);
        den += (e0 + e1) + (e2 + e3);
    }
    for (; j < end; j++) {
        int s0 = g_csrc[j];
        float e0 = __expf(lrelu(g_as1[s0 * 4 + h] + adh));
        float4 v0 = *(const float4*)(g_xw1 + (size_t)s0 * 128 + c0);
        acc.x = fmaf(e0, v0.x, acc.x); acc.y = fmaf(e0, v0.y, acc.y);
        acc.z = fmaf(e0, v0.z, acc.z); acc.w = fmaf(e0, v0.w, acc.w);
        den += e0;
    }
    float inv = 1.0f / (den + 1e-16f);
    float4 bv = *(const float4*)(b1 + c0);
    float4 hv;
    hv.x = acc.x * inv + bv.x; hv.x = hv.x > 0.f ? hv.x : expm1f(hv.x);
    hv.y = acc.y * inv + bv.y; hv.y = hv.y > 0.f ? hv.y : expm1f(hv.y);
    hv.z = acc.z * inv + bv.z; hv.z = hv.z > 0.f ? hv.z : expm1f(hv.z);
    hv.w = acc.w * inv + bv.w; hv.w = hv.w > 0.f ? hv.w : expm1f(hv.w);
    *(float4*)(g_h + (size_t)nd * 128 + c0) = hv;
}

// xw2 = h @ W2; a_src2/a_dst2. 4 nodes per warp.
__global__ void k_gemm2(const float* __restrict__ W,
                        const float* __restrict__ asv, const float* __restrict__ adv, int n) {
    __shared__ float hs[32][128];
    int w = threadIdx.x >> 5, lane = threadIdx.x & 31;
    int node0 = blockIdx.x * 32 + w * 4;
    int c0 = lane * 4;
#pragma unroll
    for (int i = 0; i < 4; i++) {
        int nd = node0 + i;
        if (nd < n)
            ((float4*)hs[w * 4 + i])[lane] = *(const float4*)(g_h + (size_t)nd * 128 + c0);
    }
    __syncwarp();
    float2 acc0 = make_float2(0,0), acc1 = acc0, acc2 = acc0, acc3 = acc0;
    const float* wp = W + lane * 2;
#pragma unroll 4
    for (int k = 0; k < 128; k++) {
        float2 wv = *(const float2*)(wp + k * 64);
        float x0 = hs[w*4+0][k], x1 = hs[w*4+1][k], x2 = hs[w*4+2][k], x3 = hs[w*4+3][k];
        acc0.x = fmaf(x0, wv.x, acc0.x); acc0.y = fmaf(x0, wv.y, acc0.y);
        acc1.x = fmaf(x1, wv.x, acc1.x); acc1.y = fmaf(x1, wv.y, acc1.y);
        acc2.x = fmaf(x2, wv.x, acc2.x); acc2.y = fmaf(x2, wv.y, acc2.y);
        acc3.x = fmaf(x3, wv.x, acc3.x); acc3.y = fmaf(x3, wv.y, acc3.y);
    }
    float2 av = *(const float2*)(asv + lane * 2);
    float2 dv = *(const float2*)(adv + lane * 2);
    float2 accs[4] = {acc0, acc1, acc2, acc3};
#pragma unroll
    for (int i = 0; i < 4; i++) {
        int nd = node0 + i;
        if (nd >= n) continue;
        float2 a = accs[i];
        *(float2*)(g_xw2 + (size_t)nd * 64 + lane * 2) = a;
        float s = a.x * av.x + a.y * av.y;
        float d = a.x * dv.x + a.y * dv.y;
#pragma unroll
        for (int off = 16; off; off >>= 1) {
            s += __shfl_xor_sync(0xffffffffu, s, off);
            d += __shfl_xor_sync(0xffffffffu, d, off);
        }
        if (lane == 0) { g_as2[nd] = s; g_ad2[nd] = d; }
    }
}

// gather agg layer2: warp per dst node.
__global__ void k_agg2(int n) {
    int gt = blockIdx.x * blockDim.x + threadIdx.x;
    int nd = gt >> 5, lane = gt & 31;
    if (nd >= n) return;
    int c0 = lane * 2;
    int beg = g_rowst[nd], end = g_rowst[nd + 1];
    float adh = g_ad2[nd];
    float2 acc = make_float2(0,0);
    float den = 0.f;
    int j = beg;
    for (; j + 1 < end; j += 2) {
        int s0 = g_csrc[j], s1 = g_csrc[j + 1];
        float e0 = __expf(lrelu(g_as2[s0] + adh));
        float e1 = __expf(lrelu(g_as2[s1] + adh));
        float2 v0 = *(const float2*)(g_xw2 + (size_t)s0 * 64 + c0);
        float2 v1 = *(const float2*)(g_xw2 + (size_t)s1 * 64 + c0);
        acc.x = fmaf(e0, v0.x, acc.x); acc.y = fmaf(e0, v0.y, acc.y);
        acc.x = fmaf(e1, v1.x, acc.x); acc.y = fmaf(e1, v1.y, acc.y);
        den += e0 + e1;
    }
    if (j < end) {
        int s0 = g_csrc[j];
        float e0 = __expf(lrelu(g_as2[s0] + adh));
        float2 v0 = *(const float2*)(g_xw2 + (size_t)s0 * 64 + c0);
        acc.x = fmaf(e0, v0.x, acc.x); acc.y = fmaf(e0, v0.y, acc.y);
        den += e0;
    }
    float inv = 1.0f / (den + 1e-16f);
    *(float2*)(g_out2 + (size_t)nd * 64 + c0) = make_float2(acc.x * inv, acc.y * inv);
}

// final: dout[c] = b2[c] (seeded in init) + mean_n out2[n][c]
__global__ void k_final(float* __restrict__ dout, int n) {
    __shared__ float sm[256];
    int tid = threadIdx.x;
    float local = 0.f;
    float inv = 1.0f / (float)n;
    int total = n * 64;
    for (int i = blockIdx.x * 256 + tid; i < total; i += gridDim.x * 256)
        local += g_out2[i] * inv;
    sm[tid] = local;
    __syncthreads();
    if (tid < 64) {
        float s2 = sm[tid] + sm[tid + 64] + sm[tid + 128] + sm[tid + 192];
        atomicAdd(&dout[tid], s2);
    }
}

// ---------------- launch ----------------
extern "C" void kernel_launch(void* const* d_in, const int* in_sizes, int n_in,
                              void* d_out, int out_size) {
    const float* x   = (const float*)d_in[0];
    const int*   ei  = (const int*)d_in[1];
    const float* W1  = (const float*)d_in[2];
    const float* as1 = (const float*)d_in[3];
    const float* ad1 = (const float*)d_in[4];
    const float* b1  = (const float*)d_in[5];
    const float* W2  = (const float*)d_in[6];
    const float* as2 = (const float*)d_in[7];
    const float* ad2 = (const float*)d_in[8];
    const float* b2  = (const float*)d_in[9];
    float* out = (float*)d_out;

    int n = in_sizes[0] / 128;
    int E = in_sizes[1] / 2;
    int Etot = E + n;
    int nb = (n + SCAN_BLK - 1) / SCAN_BLK;

    // one-time stream/event resources (no device-memory allocation; the
    // launched work is identical on every call)
    static cudaStream_t s2 = nullptr;
    static cudaEvent_t evFork = nullptr, evJoin = nullptr;
    if (s2 == nullptr) {
        cudaStreamCreateWithFlags(&s2, cudaStreamNonBlocking);
        cudaEventCreateWithFlags(&evFork, cudaEventDisableTiming);
        cudaEventCreateWithFlags(&evJoin, cudaEventDisableTiming);
    }

    // fork: gemm1 runs on s2 concurrently with the CSR build on the main stream
    cudaEventRecord(evFork, 0);
    cudaStreamWaitEvent(s2, evFork, 0);
    k_gemm1<<<(n + 31) / 32, 256, 0, s2>>>(x, W1, as1, ad1, n);
    cudaEventRecord(evJoin, s2);

    // CSR build chain on the main stream
    k_init      <<<(n + 255) / 256, 256>>>(b2, out, n);
    k_hist      <<<(Etot + 255) / 256, 256>>>(ei, E, Etot);
    k_scan_local<<<nb, SCAN_BLK>>>(n);
    k_scan_spine<<<1, MAX_SCAN_BLOCKS>>>(nb, n);
    k_scan_add  <<<(n + 255) / 256, 256>>>(n);
    k_scatter   <<<(Etot + 255) / 256, 256>>>(ei, E, Etot);

    // join: agg1 needs both CSR and gemm1 outputs
    cudaStreamWaitEvent(0, evJoin, 0);
    k_agg1 <<<(n + 7) / 8, 256>>>(b1, n);
    k_gemm2<<<(n + 31) / 32, 256>>>(W2, as2, ad2, n);
    k_agg2 <<<(n + 7) / 8, 256>>>(n);
    k_final<<<256, 256>>>(out, n);
}

// round 9
// speedup vs baseline: 1.4836x; 1.0058x over previous
#include <cuda_runtime.h>
#include <cuda_fp16.h>
#include <math.h>

// ---------------- problem constants ----------------
#define NMAX 50000
#define EMAX 1700000   // 1.6M edges + 50k self-loops
#define SCAN_BLK 512
#define MAX_SCAN_BLOCKS 128   // ceil(NMAX/SCAN_BLK) = 98

// ---------------- device scratch (no allocs allowed) ----------------
__device__ uint2    g_xw1h[NMAX * 32];   // 128 cols as half (4 per lane-slot)
__device__ float    g_as1 [NMAX * 4];
__device__ float    g_ad1 [NMAX * 4];
__device__ float    g_h   [NMAX * 128];  // elu(normalized agg1 + b1)
__device__ unsigned g_xw2h[NMAX * 32];   // 64 cols as half (2 per slot)
__device__ float    g_as2 [NMAX];
__device__ float    g_ad2 [NMAX];
__device__ float    g_out2[NMAX * 64];

// CSR by destination (built once per call, shared by both layers)
__device__ int g_cnt   [NMAX];
__device__ int g_excl  [NMAX];
__device__ int g_blksum[MAX_SCAN_BLOCKS];
__device__ int g_blkoff[MAX_SCAN_BLOCKS];
__device__ int g_rowst [NMAX + 1];
__device__ int g_cursor[NMAX];
__device__ int g_csrc  [EMAX];

__device__ __forceinline__ float lrelu(float z) { return z > 0.f ? z : 0.2f * z; }

// ---------------- CSR build (R8 proven, unchanged) ----------------
__global__ void k_init(const float* __restrict__ b2, float* __restrict__ dout, int n) {
    int i = blockIdx.x * blockDim.x + threadIdx.x;
    if (i < n)  g_cnt[i] = 0;
    if (i < 64) dout[i] = b2[i];
}

__global__ void k_hist(const int* __restrict__ ei, int E, int Etot) {
    int e = blockIdx.x * blockDim.x + threadIdx.x;
    if (e >= Etot) return;
    int d = (e < E) ? ei[E + e] : (e - E);
    atomicAdd(&g_cnt[d], 1);
}

__global__ void k_scan_local(int n) {
    __shared__ int sm[SCAN_BLK];
    int t = threadIdx.x;
    int i = blockIdx.x * SCAN_BLK + t;
    int v = (i < n) ? g_cnt[i] : 0;
    sm[t] = v;
    __syncthreads();
    for (int off = 1; off < SCAN_BLK; off <<= 1) {
        int u = (t >= off) ? sm[t - off] : 0;
        __syncthreads();
        sm[t] += u;
        __syncthreads();
    }
    if (i < n) g_excl[i] = sm[t] - v;
    if (t == SCAN_BLK - 1) g_blksum[blockIdx.x] = sm[SCAN_BLK - 1];
}

__global__ void k_scan_spine(int nb, int n) {
    __shared__ int sm[MAX_SCAN_BLOCKS];
    int t = threadIdx.x;
    int v = (t < nb) ? g_blksum[t] : 0;
    sm[t] = v;
    __syncthreads();
    for (int off = 1; off < MAX_SCAN_BLOCKS; off <<= 1) {
        int u = (t >= off) ? sm[t - off] : 0;
        __syncthreads();
        sm[t] += u;
        __syncthreads();
    }
    if (t < nb) g_blkoff[t] = sm[t] - v;
    if (t == MAX_SCAN_BLOCKS - 1) g_rowst[n] = sm[MAX_SCAN_BLOCKS - 1];
}

__global__ void k_scan_add(int n) {
    int i = blockIdx.x * blockDim.x + threadIdx.x;
    if (i >= n) return;
    int base = g_excl[i] + g_blkoff[i / SCAN_BLK];
    g_rowst[i] = base;
    g_cursor[i] = base;
}

__global__ void k_scatter(const int* __restrict__ ei, int E, int Etot) {
    int e = blockIdx.x * blockDim.x + threadIdx.x;
    if (e >= Etot) return;
    int s, d;
    if (e < E) { s = ei[e]; d = ei[E + e]; } else { s = d = e - E; }
    int pos = atomicAdd(&g_cursor[d], 1);
    g_csrc[pos] = s;
}

// ---------------- layer kernels ----------------
// xw1 = x @ W1 (half out); a_src1/a_dst1 fp32. 4 nodes per warp.
__global__ void k_gemm1(const float* __restrict__ x, const float* __restrict__ W,
                        const float* __restrict__ asv, const float* __restrict__ adv, int n) {
    __shared__ float xs[32][128];
    int w = threadIdx.x >> 5, lane = threadIdx.x & 31;
    int node0 = blockIdx.x * 32 + w * 4;
    int c0 = lane * 4;
#pragma unroll
    for (int i = 0; i < 4; i++) {
        int nd = node0 + i;
        if (nd < n)
            ((float4*)xs[w * 4 + i])[lane] = *(const float4*)(x + (size_t)nd * 128 + c0);
    }
    __syncwarp();
    float4 acc0 = make_float4(0,0,0,0), acc1 = acc0, acc2 = acc0, acc3 = acc0;
    const float* wp = W + c0;
#pragma unroll 4
    for (int k = 0; k < 128; k++) {
        float4 wv = *(const float4*)(wp + k * 128);
        float x0 = xs[w*4+0][k], x1 = xs[w*4+1][k], x2 = xs[w*4+2][k], x3 = xs[w*4+3][k];
        acc0.x = fmaf(x0, wv.x, acc0.x); acc0.y = fmaf(x0, wv.y, acc0.y);
        acc0.z = fmaf(x0, wv.z, acc0.z); acc0.w = fmaf(x0, wv.w, acc0.w);
        acc1.x = fmaf(x1, wv.x, acc1.x); acc1.y = fmaf(x1, wv.y, acc1.y);
        acc1.z = fmaf(x1, wv.z, acc1.z); acc1.w = fmaf(x1, wv.w, acc1.w);
        acc2.x = fmaf(x2, wv.x, acc2.x); acc2.y = fmaf(x2, wv.y, acc2.y);
        acc2.z = fmaf(x2, wv.z, acc2.z); acc2.w = fmaf(x2, wv.w, acc2.w);
        acc3.x = fmaf(x3, wv.x, acc3.x); acc3.y = fmaf(x3, wv.y, acc3.y);
        acc3.z = fmaf(x3, wv.z, acc3.z); acc3.w = fmaf(x3, wv.w, acc3.w);
    }
    float4 av = *(const float4*)(asv + c0);
    float4 dv = *(const float4*)(adv + c0);
    float4 accs[4] = {acc0, acc1, acc2, acc3};
#pragma unroll
    for (int i = 0; i < 4; i++) {
        int nd = node0 + i;
        if (nd >= n) continue;
        float4 a = accs[i];
        __half2 p0 = __floats2half2_rn(a.x, a.y);
        __half2 p1 = __floats2half2_rn(a.z, a.w);
        uint2 packed;
        packed.x = *(unsigned*)&p0;
        packed.y = *(unsigned*)&p1;
        g_xw1h[nd * 32 + lane] = packed;
        float s = a.x * av.x + a.y * av.y + a.z * av.z + a.w * av.w;
        float d = a.x * dv.x + a.y * dv.y + a.z * dv.z + a.w * dv.w;
#pragma unroll
        for (int off = 4; off; off >>= 1) {
            s += __shfl_xor_sync(0xffffffffu, s, off);
            d += __shfl_xor_sync(0xffffffffu, d, off);
        }
        if ((lane & 7) == 0) {
            g_as1[nd * 4 + (lane >> 3)] = s;
            g_ad1[nd * 4 + (lane >> 3)] = d;
        }
    }
}

// gather agg layer1: warp per dst node, half-compressed gather, fp32 math.
__global__ void k_agg1(const float* __restrict__ b1, int n) {
    int gt = blockIdx.x * blockDim.x + threadIdx.x;
    int nd = gt >> 5, lane = gt & 31;
    if (nd >= n) return;
    int h = lane >> 3, c0 = lane * 4;
    int beg = g_rowst[nd], end = g_rowst[nd + 1];
    float adh = g_ad1[nd * 4 + h];
    float4 acc = make_float4(0,0,0,0);
    float den = 0.f;
    int j = beg;
    for (; j + 3 < end; j += 4) {
        int s0 = g_csrc[j], s1 = g_csrc[j+1], s2 = g_csrc[j+2], s3 = g_csrc[j+3];
        float e0 = __expf(lrelu(g_as1[s0 * 4 + h] + adh));
        float e1 = __expf(lrelu(g_as1[s1 * 4 + h] + adh));
        float e2 = __expf(lrelu(g_as1[s2 * 4 + h] + adh));
        float e3 = __expf(lrelu(g_as1[s3 * 4 + h] + adh));
        uint2 r0 = g_xw1h[s0 * 32 + lane];
        uint2 r1 = g_xw1h[s1 * 32 + lane];
        uint2 r2 = g_xw1h[s2 * 32 + lane];
        uint2 r3 = g_xw1h[s3 * 32 + lane];
        float2 p0a = __half22float2(*(__half2*)&r0.x), p0b = __half22float2(*(__half2*)&r0.y);
        float2 p1a = __half22float2(*(__half2*)&r1.x), p1b = __half22float2(*(__half2*)&r1.y);
        float2 p2a = __half22float2(*(__half2*)&r2.x), p2b = __half22float2(*(__half2*)&r2.y);
        float2 p3a = __half22float2(*(__half2*)&r3.x), p3b = __half22float2(*(__half2*)&r3.y);
        acc.x = fmaf(e0, p0a.x, acc.x); acc.y = fmaf(e0, p0a.y, acc.y);
        acc.z = fmaf(e0, p0b.x, acc.z); acc.w = fmaf(e0, p0b.y, acc.w);
        acc.x = fmaf(e1, p1a.x, acc.x); acc.y = fmaf(e1, p1a.y, acc.y);
        acc.z = fmaf(e1, p1b.x, acc.z); acc.w = fmaf(e1, p1b.y, acc.w);
        acc.x = fmaf(e2, p2a.x, acc.x); acc.y = fmaf(e2, p2a.y, acc.y);
        acc.z = fmaf(e2, p2b.x, acc.z); acc.w = fmaf(e2, p2b.y, acc.w);
        acc.x = fmaf(e3, p3a.x, acc.x); acc.y = fmaf(e3, p3a.y, acc.y);
        acc.z = fmaf(e3, p3b.x, acc.z); acc.w = fmaf(e3, p3b.y, acc.w);
        den += (e0 + e1) + (e2 + e3);
    }
    for (; j < end; j++) {
        int s0 = g_csrc[j];
        float e0 = __expf(lrelu(g_as1[s0 * 4 + h] + adh));
        uint2 r0 = g_xw1h[s0 * 32 + lane];
        float2 p0a = __half22float2(*(__half2*)&r0.x), p0b = __half22float2(*(__half2*)&r0.y);
        acc.x = fmaf(e0, p0a.x, acc.x); acc.y = fmaf(e0, p0a.y, acc.y);
        acc.z = fmaf(e0, p0b.x, acc.z); acc.w = fmaf(e0, p0b.y, acc.w);
        den += e0;
    }
    float inv = 1.0f / (den + 1e-16f);
    float4 bv = *(const float4*)(b1 + c0);
    float4 hv;
    hv.x = acc.x * inv + bv.x; hv.x = hv.x > 0.f ? hv.x : expm1f(hv.x);
    hv.y = acc.y * inv + bv.y; hv.y = hv.y > 0.f ? hv.y : expm1f(hv.y);
    hv.z = acc.z * inv + bv.z; hv.z = hv.z > 0.f ? hv.z : expm1f(hv.z);
    hv.w = acc.w * inv + bv.w; hv.w = hv.w > 0.f ? hv.w : expm1f(hv.w);
    *(float4*)(g_h + (size_t)nd * 128 + c0) = hv;
}

// xw2 = h @ W2 (half out); a_src2/a_dst2 fp32. 4 nodes per warp.
__global__ void k_gemm2(const float* __restrict__ W,
                        const float* __restrict__ asv, const float* __restrict__ adv, int n) {
    __shared__ float hs[32][128];
    int w = threadIdx.x >> 5, lane = threadIdx.x & 31;
    int node0 = blockIdx.x * 32 + w * 4;
    int c0 = lane * 4;
#pragma unroll
    for (int i = 0; i < 4; i++) {
        int nd = node0 + i;
        if (nd < n)
            ((float4*)hs[w * 4 + i])[lane] = *(const float4*)(g_h + (size_t)nd * 128 + c0);
    }
    __syncwarp();
    float2 acc0 = make_float2(0,0), acc1 = acc0, acc2 = acc0, acc3 = acc0;
    const float* wp = W + lane * 2;
#pragma unroll 4
    for (int k = 0; k < 128; k++) {
        float2 wv = *(const float2*)(wp + k * 64);
        float x0 = hs[w*4+0][k], x1 = hs[w*4+1][k], x2 = hs[w*4+2][k], x3 = hs[w*4+3][k];
        acc0.x = fmaf(x0, wv.x, acc0.x); acc0.y = fmaf(x0, wv.y, acc0.y);
        acc1.x = fmaf(x1, wv.x, acc1.x); acc1.y = fmaf(x1, wv.y, acc1.y);
        acc2.x = fmaf(x2, wv.x, acc2.x); acc2.y = fmaf(x2, wv.y, acc2.y);
        acc3.x = fmaf(x3, wv.x, acc3.x); acc3.y = fmaf(x3, wv.y, acc3.y);
    }
    float2 av = *(const float2*)(asv + lane * 2);
    float2 dv = *(const float2*)(adv + lane * 2);
    float2 accs[4] = {acc0, acc1, acc2, acc3};
#pragma unroll
    for (int i = 0; i < 4; i++) {
        int nd = node0 + i;
        if (nd >= n) continue;
        float2 a = accs[i];
        __half2 p = __floats2half2_rn(a.x, a.y);
        g_xw2h[nd * 32 + lane] = *(unsigned*)&p;
        float s = a.x * av.x + a.y * av.y;
        float d = a.x * dv.x + a.y * dv.y;
#pragma unroll
        for (int off = 16; off; off >>= 1) {
            s += __shfl_xor_sync(0xffffffffu, s, off);
            d += __shfl_xor_sync(0xffffffffu, d, off);
        }
        if (lane == 0) { g_as2[nd] = s; g_ad2[nd] = d; }
    }
}

// gather agg layer2: warp per dst node, half gather; writes normalized out2.
__global__ void k_agg2(int n) {
    int gt = blockIdx.x * blockDim.x + threadIdx.x;
    int nd = gt >> 5, lane = gt & 31;
    if (nd >= n) return;
    int c0 = lane * 2;
    int beg = g_rowst[nd], end = g_rowst[nd + 1];
    float adh = g_ad2[nd];
    float2 acc = make_float2(0,0);
    float den = 0.f;
    int j = beg;
    for (; j + 1 < end; j += 2) {
        int s0 = g_csrc[j], s1 = g_csrc[j + 1];
        float e0 = __expf(lrelu(g_as2[s0] + adh));
        float e1 = __expf(lrelu(g_as2[s1] + adh));
        unsigned r0 = g_xw2h[s0 * 32 + lane];
        unsigned r1 = g_xw2h[s1 * 32 + lane];
        float2 v0 = __half22float2(*(__half2*)&r0);
        float2 v1 = __half22float2(*(__half2*)&r1);
        acc.x = fmaf(e0, v0.x, acc.x); acc.y = fmaf(e0, v0.y, acc.y);
        acc.x = fmaf(e1, v1.x, acc.x); acc.y = fmaf(e1, v1.y, acc.y);
        den += e0 + e1;
    }
    if (j < end) {
        int s0 = g_csrc[j];
        float e0 = __expf(lrelu(g_as2[s0] + adh));
        unsigned r0 = g_xw2h[s0 * 32 + lane];
        float2 v0 = __half22float2(*(__half2*)&r0);
        acc.x = fmaf(e0, v0.x, acc.x); acc.y = fmaf(e0, v0.y, acc.y);
        den += e0;
    }
    float inv = 1.0f / (den + 1e-16f);
    *(float2*)(g_out2 + (size_t)nd * 64 + c0) = make_float2(acc.x * inv, acc.y * inv);
}

// final: dout[c] = b2[c] (seeded in init) + mean_n out2[n][c]
__global__ void k_final(float* __restrict__ dout, int n) {
    __shared__ float sm[256];
    int tid = threadIdx.x;
    float local = 0.f;
    float inv = 1.0f / (float)n;
    int total = n * 64;
    for (int i = blockIdx.x * 256 + tid; i < total; i += gridDim.x * 256)
        local += g_out2[i] * inv;
    sm[tid] = local;
    __syncthreads();
    if (tid < 64) {
        float s2 = sm[tid] + sm[tid + 64] + sm[tid + 128] + sm[tid + 192];
        atomicAdd(&dout[tid], s2);
    }
}

// ---------------- launch ----------------
extern "C" void kernel_launch(void* const* d_in, const int* in_sizes, int n_in,
                              void* d_out, int out_size) {
    const float* x   = (const float*)d_in[0];
    const int*   ei  = (const int*)d_in[1];
    const float* W1  = (const float*)d_in[2];
    const float* as1 = (const float*)d_in[3];
    const float* ad1 = (const float*)d_in[4];
    const float* b1  = (const float*)d_in[5];
    const float* W2  = (const float*)d_in[6];
    const float* as2 = (const float*)d_in[7];
    const float* ad2 = (const float*)d_in[8];
    const float* b2  = (const float*)d_in[9];
    float* out = (float*)d_out;

    int n = in_sizes[0] / 128;
    int E = in_sizes[1] / 2;
    int Etot = E + n;
    int nb = (n + SCAN_BLK - 1) / SCAN_BLK;

    // one-time stream/event resources (no device-memory allocation; the
    // launched work is identical on every call)
    static cudaStream_t s2 = nullptr;
    static cudaEvent_t evFork = nullptr, evJoin = nullptr;
    if (s2 == nullptr) {
        cudaStreamCreateWithFlags(&s2, cudaStreamNonBlocking);
        cudaEventCreateWithFlags(&evFork, cudaEventDisableTiming);
        cudaEventCreateWithFlags(&evJoin, cudaEventDisableTiming);
    }

    // fork: gemm1 runs on s2 concurrently with the CSR build on the main stream
    cudaEventRecord(evFork, 0);
    cudaStreamWaitEvent(s2, evFork, 0);
    k_gemm1<<<(n + 31) / 32, 256, 0, s2>>>(x, W1, as1, ad1, n);
    cudaEventRecord(evJoin, s2);

    // CSR build chain on the main stream
    k_init      <<<(n + 255) / 256, 256>>>(b2, out, n);
    k_hist      <<<(Etot + 255) / 256, 256>>>(ei, E, Etot);
    k_scan_local<<<nb, SCAN_BLK>>>(n);
    k_scan_spine<<<1, MAX_SCAN_BLOCKS>>>(nb, n);
    k_scan_add  <<<(n + 255) / 256, 256>>>(n);
    k_scatter   <<<(Etot + 255) / 256, 256>>>(ei, E, Etot);

    // join: agg1 needs both CSR and gemm1 outputs
    cudaStreamWaitEvent(0, evJoin, 0);
    k_agg1 <<<(n + 7) / 8, 256>>>(b1, n);
    k_gemm2<<<(n + 31) / 32, 256>>>(W2, as2, ad2, n);
    k_agg2 <<<(n + 7) / 8, 256>>>(n);
    k_final<<<256, 256>>>(out, n);
}

// round 10
// speedup vs baseline: 1.5047x; 1.0142x over previous
#include <cuda_runtime.h>
#include <math.h>

// ---------------- problem constants ----------------
#define NMAX 50000
#define EMAX 1700000   // 1.6M edges + 50k self-loops
#define SCAN_BLK 512
#define MAX_SCAN_BLOCKS 128   // ceil(NMAX/SCAN_BLK) = 98

// ---------------- device scratch (no allocs allowed) ----------------
__device__ float g_xw1 [NMAX * 128];
__device__ float g_as1 [NMAX * 4];
__device__ float g_ad1 [NMAX * 4];
__device__ float g_h   [NMAX * 128];   // elu(normalized agg1 + b1)
__device__ float g_xw2 [NMAX * 64];
__device__ float g_as2 [NMAX];
__device__ float g_ad2 [NMAX];
__device__ float g_out2[NMAX * 64];

// CSR by destination (built once per call, shared by both layers)
__device__ int g_cnt   [NMAX];
__device__ int g_excl  [NMAX];
__device__ int g_blksum[MAX_SCAN_BLOCKS];
__device__ int g_blkoff[MAX_SCAN_BLOCKS];
__device__ int g_rowst [NMAX + 1];
__device__ int g_cursor[NMAX];
__device__ int g_csrc  [EMAX];

__device__ __forceinline__ float lrelu(float z) { return z > 0.f ? z : 0.2f * z; }

// ---------------- CSR build (proven, unchanged) ----------------
__global__ void k_init(const float* __restrict__ b2, float* __restrict__ dout, int n) {
    int i = blockIdx.x * blockDim.x + threadIdx.x;
    if (i < n)  g_cnt[i] = 0;
    if (i < 64) dout[i] = b2[i];
}

__global__ void k_hist(const int* __restrict__ ei, int E, int Etot) {
    int e = blockIdx.x * blockDim.x + threadIdx.x;
    if (e >= Etot) return;
    int d = (e < E) ? ei[E + e] : (e - E);
    atomicAdd(&g_cnt[d], 1);
}

__global__ void k_scan_local(int n) {
    __shared__ int sm[SCAN_BLK];
    int t = threadIdx.x;
    int i = blockIdx.x * SCAN_BLK + t;
    int v = (i < n) ? g_cnt[i] : 0;
    sm[t] = v;
    __syncthreads();
    for (int off = 1; off < SCAN_BLK; off <<= 1) {
        int u = (t >= off) ? sm[t - off] : 0;
        __syncthreads();
        sm[t] += u;
        __syncthreads();
    }
    if (i < n) g_excl[i] = sm[t] - v;
    if (t == SCAN_BLK - 1) g_blksum[blockIdx.x] = sm[SCAN_BLK - 1];
}

__global__ void k_scan_spine(int nb, int n) {
    __shared__ int sm[MAX_SCAN_BLOCKS];
    int t = threadIdx.x;
    int v = (t < nb) ? g_blksum[t] : 0;
    sm[t] = v;
    __syncthreads();
    for (int off = 1; off < MAX_SCAN_BLOCKS; off <<= 1) {
        int u = (t >= off) ? sm[t - off] : 0;
        __syncthreads();
        sm[t] += u;
        __syncthreads();
    }
    if (t < nb) g_blkoff[t] = sm[t] - v;
    if (t == MAX_SCAN_BLOCKS - 1) g_rowst[n] = sm[MAX_SCAN_BLOCKS - 1];
}

__global__ void k_scan_add(int n) {
    int i = blockIdx.x * blockDim.x + threadIdx.x;
    if (i >= n) return;
    int base = g_excl[i] + g_blkoff[i / SCAN_BLK];
    g_rowst[i] = base;
    g_cursor[i] = base;
}

__global__ void k_scatter(const int* __restrict__ ei, int E, int Etot) {
    int e = blockIdx.x * blockDim.x + threadIdx.x;
    if (e >= Etot) return;
    int s, d;
    if (e < E) { s = ei[e]; d = ei[E + e]; } else { s = d = e - E; }
    int pos = atomicAdd(&g_cursor[d], 1);
    g_csrc[pos] = s;
}

// ---------------- layer kernels ----------------
// xw1 = x @ W1 ; a_src1/a_dst1. 4 nodes per warp (fp32 out, R8 proven).
__global__ void k_gemm1(const float* __restrict__ x, const float* __restrict__ W,
                        const float* __restrict__ asv, const float* __restrict__ adv, int n) {
    __shared__ float xs[32][128];
    int w = threadIdx.x >> 5, lane = threadIdx.x & 31;
    int node0 = blockIdx.x * 32 + w * 4;
    int c0 = lane * 4;
#pragma unroll
    for (int i = 0; i < 4; i++) {
        int nd = node0 + i;
        if (nd < n)
            ((float4*)xs[w * 4 + i])[lane] = *(const float4*)(x + (size_t)nd * 128 + c0);
    }
    __syncwarp();
    float4 acc0 = make_float4(0,0,0,0), acc1 = acc0, acc2 = acc0, acc3 = acc0;
    const float* wp = W + c0;
#pragma unroll 4
    for (int k = 0; k < 128; k++) {
        float4 wv = *(const float4*)(wp + k * 128);
        float x0 = xs[w*4+0][k], x1 = xs[w*4+1][k], x2 = xs[w*4+2][k], x3 = xs[w*4+3][k];
        acc0.x = fmaf(x0, wv.x, acc0.x); acc0.y = fmaf(x0, wv.y, acc0.y);
        acc0.z = fmaf(x0, wv.z, acc0.z); acc0.w = fmaf(x0, wv.w, acc0.w);
        acc1.x = fmaf(x1, wv.x, acc1.x); acc1.y = fmaf(x1, wv.y, acc1.y);
        acc1.z = fmaf(x1, wv.z, acc1.z); acc1.w = fmaf(x1, wv.w, acc1.w);
        acc2.x = fmaf(x2, wv.x, acc2.x); acc2.y = fmaf(x2, wv.y, acc2.y);
        acc2.z = fmaf(x2, wv.z, acc2.z); acc2.w = fmaf(x2, wv.w, acc2.w);
        acc3.x = fmaf(x3, wv.x, acc3.x); acc3.y = fmaf(x3, wv.y, acc3.y);
        acc3.z = fmaf(x3, wv.z, acc3.z); acc3.w = fmaf(x3, wv.w, acc3.w);
    }
    float4 av = *(const float4*)(asv + c0);
    float4 dv = *(const float4*)(adv + c0);
    float4 accs[4] = {acc0, acc1, acc2, acc3};
#pragma unroll
    for (int i = 0; i < 4; i++) {
        int nd = node0 + i;
        if (nd >= n) continue;
        float4 a = accs[i];
        *(float4*)(g_xw1 + (size_t)nd * 128 + c0) = a;
        float s = a.x * av.x + a.y * av.y + a.z * av.z + a.w * av.w;
        float d = a.x * dv.x + a.y * dv.y + a.z * dv.z + a.w * dv.w;
#pragma unroll
        for (int off = 4; off; off >>= 1) {
            s += __shfl_xor_sync(0xffffffffu, s, off);
            d += __shfl_xor_sync(0xffffffffu, d, off);
        }
        if ((lane & 7) == 0) {
            g_as1[nd * 4 + (lane >> 3)] = s;
            g_ad1[nd * 4 + (lane >> 3)] = d;
        }
    }
}

// gather agg layer1: warp per node, 8-edge groups with lane-cooperative loads.
// LDGs per edge: 1 csrc/8 + 1 as1/8 + 1 feature = 1.25 (was 3).
__global__ void k_agg1(const float* __restrict__ b1, int n) {
    int gt = blockIdx.x * blockDim.x + threadIdx.x;
    int nd = gt >> 5, lane = gt & 31;
    if (nd >= n) return;
    int c0 = lane * 4;
    int hsel = lane >> 3;                 // head for my columns
    int beg = g_rowst[nd], end = g_rowst[nd + 1];
    float adh_al = g_ad1[nd * 4 + (lane & 3)];  // ad for logit-layout lane
    float4 acc = make_float4(0,0,0,0);
    float den = 0.f;
    for (int j = beg; j < end; j += 8) {
        int m = end - j;                  // edges this group (may exceed 8)
        // one LDG: 8 csrc values live in lanes (mod 8)
        int jj = j + (lane & 7);
        if (jj > end - 1) jj = end - 1;
        int sE = g_csrc[jj];
        // broadcast the 8 source ids; issue all 8 feature loads (MLP=8)
        int sk[8];
#pragma unroll
        for (int k = 0; k < 8; k++) sk[k] = __shfl_sync(0xffffffffu, sE, k);
        float4 v[8];
#pragma unroll
        for (int k = 0; k < 8; k++)
            v[k] = *(const float4*)(g_xw1 + (size_t)sk[k] * 128 + c0);
        // one LDG covers all 8 edges x 4 heads of logits; one expf instruction
        int sA = __shfl_sync(0xffffffffu, sE, lane >> 2);
        float z = g_as1[sA * 4 + (lane & 3)] + adh_al;
        float e = __expf(lrelu(z));
        if ((lane >> 2) >= m) e = 0.f;    // zero invalid tail edges
        // accumulate: route e to column lanes, 4 FMAs per edge
#pragma unroll
        for (int k = 0; k < 8; k++) {
            float ek = __shfl_sync(0xffffffffu, e, k * 4 + hsel);
            acc.x = fmaf(ek, v[k].x, acc.x);
            acc.y = fmaf(ek, v[k].y, acc.y);
            acc.z = fmaf(ek, v[k].z, acc.z);
            acc.w = fmaf(ek, v[k].w, acc.w);
            den += ek;
        }
    }
    float inv = 1.0f / (den + 1e-16f);
    float4 bv = *(const float4*)(b1 + c0);
    float4 hv;
    hv.x = acc.x * inv + bv.x; hv.x = hv.x > 0.f ? hv.x : expm1f(hv.x);
    hv.y = acc.y * inv + bv.y; hv.y = hv.y > 0.f ? hv.y : expm1f(hv.y);
    hv.z = acc.z * inv + bv.z; hv.z = hv.z > 0.f ? hv.z : expm1f(hv.z);
    hv.w = acc.w * inv + bv.w; hv.w = hv.w > 0.f ? hv.w : expm1f(hv.w);
    *(float4*)(g_h + (size_t)nd * 128 + c0) = hv;
}

// xw2 = h @ W2; a_src2/a_dst2. 4 nodes per warp (fp32 out, R8 proven).
__global__ void k_gemm2(const float* __restrict__ W,
                        const float* __restrict__ asv, const float* __restrict__ adv, int n) {
    __shared__ float hs[32][128];
    int w = threadIdx.x >> 5, lane = threadIdx.x & 31;
    int node0 = blockIdx.x * 32 + w * 4;
    int c0 = lane * 4;
#pragma unroll
    for (int i = 0; i < 4; i++) {
        int nd = node0 + i;
        if (nd < n)
            ((float4*)hs[w * 4 + i])[lane] = *(const float4*)(g_h + (size_t)nd * 128 + c0);
    }
    __syncwarp();
    float2 acc0 = make_float2(0,0), acc1 = acc0, acc2 = acc0, acc3 = acc0;
    const float* wp = W + lane * 2;
#pragma unroll 4
    for (int k = 0; k < 128; k++) {
        float2 wv = *(const float2*)(wp + k * 64);
        float x0 = hs[w*4+0][k], x1 = hs[w*4+1][k], x2 = hs[w*4+2][k], x3 = hs[w*4+3][k];
        acc0.x = fmaf(x0, wv.x, acc0.x); acc0.y = fmaf(x0, wv.y, acc0.y);
        acc1.x = fmaf(x1, wv.x, acc1.x); acc1.y = fmaf(x1, wv.y, acc1.y);
        acc2.x = fmaf(x2, wv.x, acc2.x); acc2.y = fmaf(x2, wv.y, acc2.y);
        acc3.x = fmaf(x3, wv.x, acc3.x); acc3.y = fmaf(x3, wv.y, acc3.y);
    }
    float2 av = *(const float2*)(asv + lane * 2);
    float2 dv = *(const float2*)(adv + lane * 2);
    float2 accs[4] = {acc0, acc1, acc2, acc3};
#pragma unroll
    for (int i = 0; i < 4; i++) {
        int nd = node0 + i;
        if (nd >= n) continue;
        float2 a = accs[i];
        *(float2*)(g_xw2 + (size_t)nd * 64 + lane * 2) = a;
        float s = a.x * av.x + a.y * av.y;
        float d = a.x * dv.x + a.y * dv.y;
#pragma unroll
        for (int off = 16; off; off >>= 1) {
            s += __shfl_xor_sync(0xffffffffu, s, off);
            d += __shfl_xor_sync(0xffffffffu, d, off);
        }
        if (lane == 0) { g_as2[nd] = s; g_ad2[nd] = d; }
    }
}

// gather agg layer2: warp per node, 8-edge groups, lane-cooperative loads.
__global__ void k_agg2(int n) {
    int gt = blockIdx.x * blockDim.x + threadIdx.x;
    int nd = gt >> 5, lane = gt & 31;
    if (nd >= n) return;
    int c0 = lane * 2;
    int beg = g_rowst[nd], end = g_rowst[nd + 1];
    float adh = g_ad2[nd];
    float2 acc = make_float2(0,0);
    float den = 0.f;
    for (int j = beg; j < end; j += 8) {
        int m = end - j;
        int jj = j + (lane & 7);
        if (jj > end - 1) jj = end - 1;
        int sE = g_csrc[jj];
        int sk[8];
#pragma unroll
        for (int k = 0; k < 8; k++) sk[k] = __shfl_sync(0xffffffffu, sE, k);
        float2 v[8];
#pragma unroll
        for (int k = 0; k < 8; k++)
            v[k] = *(const float2*)(g_xw2 + (size_t)sk[k] * 64 + c0);
        // logits: lanes 0-7 each hold one edge's as2; single LDG + expf
        float z = g_as2[sE] + adh;        // every lane loads its own (8 distinct)
        float e = __expf(lrelu(z));
        if ((lane & 7) >= m) e = 0.f;
#pragma unroll
        for (int k = 0; k < 8; k++) {
            float ek = __shfl_sync(0xffffffffu, e, k);
            acc.x = fmaf(ek, v[k].x, acc.x);
            acc.y = fmaf(ek, v[k].y, acc.y);
            den += ek;
        }
    }
    float inv = 1.0f / (den + 1e-16f);
    *(float2*)(g_out2 + (size_t)nd * 64 + c0) = make_float2(acc.x * inv, acc.y * inv);
}

// final: dout[c] = b2[c] (seeded in init) + mean_n out2[n][c]
__global__ void k_final(float* __restrict__ dout, int n) {
    __shared__ float sm[256];
    int tid = threadIdx.x;
    float local = 0.f;
    float inv = 1.0f / (float)n;
    int total = n * 64;
    for (int i = blockIdx.x * 256 + tid; i < total; i += gridDim.x * 256)
        local += g_out2[i] * inv;
    sm[tid] = local;
    __syncthreads();
    if (tid < 64) {
        float s2 = sm[tid] + sm[tid + 64] + sm[tid + 128] + sm[tid + 192];
        atomicAdd(&dout[tid], s2);
    }
}

// ---------------- launch ----------------
extern "C" void kernel_launch(void* const* d_in, const int* in_sizes, int n_in,
                              void* d_out, int out_size) {
    const float* x   = (const float*)d_in[0];
    const int*   ei  = (const int*)d_in[1];
    const float* W1  = (const float*)d_in[2];
    const float* as1 = (const float*)d_in[3];
    const float* ad1 = (const float*)d_in[4];
    const float* b1  = (const float*)d_in[5];
    const float* W2  = (const float*)d_in[6];
    const float* as2 = (const float*)d_in[7];
    const float* ad2 = (const float*)d_in[8];
    const float* b2  = (const float*)d_in[9];
    float* out = (float*)d_out;

    int n = in_sizes[0] / 128;
    int E = in_sizes[1] / 2;
    int Etot = E + n;
    int nb = (n + SCAN_BLK - 1) / SCAN_BLK;

    // one-time stream/event resources (no device-memory allocation; the
    // launched work is identical on every call)
    static cudaStream_t s2 = nullptr;
    static cudaEvent_t evFork = nullptr, evJoin = nullptr;
    if (s2 == nullptr) {
        cudaStreamCreateWithFlags(&s2, cudaStreamNonBlocking);
        cudaEventCreateWithFlags(&evFork, cudaEventDisableTiming);
        cudaEventCreateWithFlags(&evJoin, cudaEventDisableTiming);
    }

    // fork: gemm1 runs on s2 concurrently with the CSR build on the main stream
    cudaEventRecord(evFork, 0);
    cudaStreamWaitEvent(s2, evFork, 0);
    k_gemm1<<<(n + 31) / 32, 256, 0, s2>>>(x, W1, as1, ad1, n);
    cudaEventRecord(evJoin, s2);

    // CSR build chain on the main stream
    k_init      <<<(n + 255) / 256, 256>>>(b2, out, n);
    k_hist      <<<(Etot + 255) / 256, 256>>>(ei, E, Etot);
    k_scan_local<<<nb, SCAN_BLK>>>(n);
    k_scan_spine<<<1, MAX_SCAN_BLOCKS>>>(nb, n);
    k_scan_add  <<<(n + 255) / 256, 256>>>(n);
    k_scatter   <<<(Etot + 255) / 256, 256>>>(ei, E, Etot);

    // join: agg1 needs both CSR and gemm1 outputs
    cudaStreamWaitEvent(0, evJoin, 0);
    k_agg1 <<<(n + 7) / 8, 256>>>(b1, n);
    k_gemm2<<<(n + 31) / 32, 256>>>(W2, as2, ad2, n);
    k_agg2 <<<(n + 7) / 8, 256>>>(n);
    k_final<<<256, 256>>>(out, n);
}